// round 11
// baseline (speedup 1.0000x reference)
#include <cuda_runtime.h>
#include <cuda_fp16.h>
#include <math.h>
#include <stdint.h>

#define BATCH 8
#define SEQ   1024
#define DIM   768
#define HEADS 12
#define HDIM  64
#define M_ROWS (BATCH*SEQ)        // 8192
#define N_QKV  (3*DIM)            // 2304
#define NKT    (DIM/32)           // 24 k-tiles of 32

#define DINLINE __device__ __forceinline__

// ---------------- scratch planes (device-code references ONLY) ----------------
// fp16 2-term scheme: A-side operands stored as (hi,lo) pairs; B-side single fp16.
#define QKV_ELEMS (BATCH*HEADS*SEQ*HDIM)
__device__ __half g_q_hi[QKV_ELEMS], g_q_lo[QKV_ELEMS];   // Q: A-side of QK^T -> pair
__device__ __half g_k_hi[QKV_ELEMS];                      // K: B-side -> single
__device__ __half g_v_hi[QKV_ELEMS];                      // V: B-side -> single
__device__ __half g_o_hi[M_ROWS*DIM], g_o_lo[M_ROWS*DIM]; // O: A-side of proj -> pair
__device__ __half g_x_hi[M_ROWS*DIM], g_x_lo[M_ROWS*DIM]; // x: A-side -> pair
__device__ __half g_wq_hi[N_QKV*DIM];                     // w_qkv^T [N][K]: B-side single
__device__ __half g_wp_hi[DIM*DIM];                       // w_proj^T [N][K]: B-side single

// ---------------- PTX helpers ----------------
DINLINE uint32_t smem_u32(const void* p) { return (uint32_t)__cvta_generic_to_shared(p); }

DINLINE void ldsm4(uint32_t r[4], uint32_t a) {
    asm volatile("ldmatrix.sync.aligned.m8n8.x4.shared.b16 {%0,%1,%2,%3},[%4];"
                 : "=r"(r[0]), "=r"(r[1]), "=r"(r[2]), "=r"(r[3]) : "r"(a));
}
DINLINE void ldsm4t(uint32_t r[4], uint32_t a) {
    asm volatile("ldmatrix.sync.aligned.m8n8.x4.trans.shared.b16 {%0,%1,%2,%3},[%4];"
                 : "=r"(r[0]), "=r"(r[1]), "=r"(r[2]), "=r"(r[3]) : "r"(a));
}
DINLINE void mma16816(float c[4], const uint32_t a[4], const uint32_t b[2]) {
    asm volatile("mma.sync.aligned.m16n8k16.row.col.f32.f16.f16.f32 "
                 "{%0,%1,%2,%3},{%4,%5,%6,%7},{%8,%9},{%0,%1,%2,%3};"
                 : "+f"(c[0]), "+f"(c[1]), "+f"(c[2]), "+f"(c[3])
                 : "r"(a[0]), "r"(a[1]), "r"(a[2]), "r"(a[3]), "r"(b[0]), "r"(b[1]));
}
DINLINE void cp16(uint32_t dst, const void* src) {
    asm volatile("cp.async.cg.shared.global [%0], [%1], 16;" :: "r"(dst), "l"(src) : "memory");
}
#define CP_COMMIT() asm volatile("cp.async.commit_group;" ::: "memory")
#define CP_WAIT1()  asm volatile("cp.async.wait_group 1;" ::: "memory")

// split fp32 pair into packed fp16 hi/lo
DINLINE void split2(float x, float y, uint32_t &hi, uint32_t &lo) {
    __half hx = __float2half_rn(x);
    __half hy = __float2half_rn(y);
    float rx = x - __half2float(hx);
    float ry = y - __half2float(hy);
    __half2 h2 = __halves2half2(hx, hy);
    __half2 l2 = __halves2half2(__float2half_rn(rx), __float2half_rn(ry));
    hi = *reinterpret_cast<uint32_t*>(&h2);
    lo = *reinterpret_cast<uint32_t*>(&l2);
}
DINLINE uint32_t pack2h(float x, float y) {
    __half2 h2 = __halves2half2(__float2half_rn(x), __float2half_rn(y));
    return *reinterpret_cast<uint32_t*>(&h2);
}

// ===========================================================================
// Prep kernels
// ===========================================================================
__global__ __launch_bounds__(256) void split_x_kernel(const float* __restrict__ x) {
    int i = blockIdx.x * 256 + threadIdx.x;   // one float4
    float4 v = ((const float4*)x)[i];
    uint32_t h0, l0, h1, l1;
    split2(v.x, v.y, h0, l0);
    split2(v.z, v.w, h1, l1);
    ((uint2*)g_x_hi)[i] = make_uint2(h0, h1);
    ((uint2*)g_x_lo)[i] = make_uint2(l0, l1);
}

// src [K][N] fp32 -> hi plane only, [N][K] fp16
template <int WSEL>
__global__ __launch_bounds__(256) void tsplit_kernel(
    const float* __restrict__ src, int K, int N)
{
    __half* dh = (WSEL == 0) ? g_wq_hi : g_wp_hi;
    __shared__ float T[32][33];
    int k0 = blockIdx.y * 32, n0 = blockIdx.x * 32;
    int tx = threadIdx.x & 31, ty = threadIdx.x >> 5;
#pragma unroll
    for (int i = 0; i < 4; i++)
        T[ty + 8 * i][tx] = src[(size_t)(k0 + ty + 8 * i) * N + n0 + tx];
    __syncthreads();
#pragma unroll
    for (int i = 0; i < 4; i++) {
        float v = T[tx][ty + 8 * i];
        dh[(size_t)(n0 + ty + 8 * i) * K + k0 + tx] = __float2half_rn(v);
    }
}

// ===========================================================================
// fp16 2-term mma.sync GEMM. Block 64x256, 4 warps, warp tile 64x64.
// BK=32, 2-stage cp.async pipeline, 2 CTAs/SM. A = pair, B = single.
// ===========================================================================
#define PAe 40                       // smem pitch in fp16 elems (80B): conflict-free
#define A_STG (64*PAe)               // 2560 elems per A plane per stage
#define B_STG (256*PAe)              // 10240 elems (single plane)
#define STG_ELEMS (2*A_STG + B_STG)  // 15360 elems
#define GEMM_SMEM_B (2 * STG_ELEMS * 2)   // 61440 bytes

template <bool QKV_EPI>
__global__ __launch_bounds__(128, 2) void mma_gemm_kernel(
    const float* __restrict__ bias, float* __restrict__ out)
{
    const __half* Ah = QKV_EPI ? g_x_hi : g_o_hi;
    const __half* Al = QKV_EPI ? g_x_lo : g_o_lo;
    const __half* Bh = QKV_EPI ? g_wq_hi : g_wp_hi;

    extern __shared__ __half sm[];
    const int tid = threadIdx.x, lane = tid & 31, warp = tid >> 5;
    const int rowBase = blockIdx.y * 64, colBase = blockIdx.x * 256;

    float acc[4][8][4];
#pragma unroll
    for (int i = 0; i < 4; i++)
#pragma unroll
        for (int j = 0; j < 8; j++)
#pragma unroll
            for (int e = 0; e < 4; e++) acc[i][j][e] = 0.f;

    auto issue = [&](int st) {
        if (st < NKT) {
            const int k0 = st * 32;
            __half* base = sm + (st & 1) * STG_ELEMS;
            // A: 64 rows x 32 cols = 256 chunks/plane, 2 iters, both planes
#pragma unroll
            for (int i = 0; i < 2; i++) {
                int id = tid + i * 128;
                int r = id >> 2, c8 = (id & 3) * 8;
                uint32_t d = smem_u32(base + r * PAe + c8);
                size_t s = (size_t)(rowBase + r) * DIM + k0 + c8;
                cp16(d, Ah + s);
                cp16(d + A_STG * 2, Al + s);
            }
            // B: 256 rows x 32 cols = 1024 chunks, hi only -> 8 iters
#pragma unroll
            for (int i = 0; i < 8; i++) {
                int id = tid + i * 128;
                int r = id >> 2, c8 = (id & 3) * 8;
                uint32_t d = smem_u32(base + 2 * A_STG + r * PAe + c8);
                cp16(d, Bh + (size_t)(colBase + r) * DIM + k0 + c8);
            }
        }
        CP_COMMIT();
    };

    issue(0);
    issue(1);

    const int a_ro = (lane & 7) + 8 * ((lane >> 3) & 1);
    const int a_co = 8 * (lane >> 4);
    const int b_ro = (lane & 7) + 8 * (lane >> 4);
    const int b_co = 8 * ((lane >> 3) & 1);

    for (int t = 0; t < NKT; t++) {
        CP_WAIT1();
        __syncthreads();
        const __half* stg = sm + (t & 1) * STG_ELEMS;
        const __half* sAh = stg;
        const __half* sAl = stg + A_STG;
        const __half* sBh = stg + 2 * A_STG;

#pragma unroll
        for (int ks = 0; ks < 2; ks++) {
            uint32_t afh[4][4], afl[4][4];
#pragma unroll
            for (int ma = 0; ma < 4; ma++) {
                int off = (ma * 16 + a_ro) * PAe + ks * 16 + a_co;
                ldsm4(afh[ma], smem_u32(sAh + off));
                ldsm4(afl[ma], smem_u32(sAl + off));
            }
#pragma unroll
            for (int nb = 0; nb < 4; nb++) {
                int off = (warp * 64 + nb * 16 + b_ro) * PAe + ks * 16 + b_co;
                uint32_t bfh[4];
                ldsm4(bfh, smem_u32(sBh + off));
#pragma unroll
                for (int ma = 0; ma < 4; ma++) {
                    mma16816(acc[ma][2*nb],   afh[ma], &bfh[0]);
                    mma16816(acc[ma][2*nb+1], afh[ma], &bfh[2]);
                    mma16816(acc[ma][2*nb],   afl[ma], &bfh[0]);
                    mma16816(acc[ma][2*nb+1], afl[ma], &bfh[2]);
                }
            }
        }
        __syncthreads();
        issue(t + 2);
    }

    // ---------------- epilogue ----------------
    const int g = lane >> 2, tq = lane & 3;
#pragma unroll
    for (int ma = 0; ma < 4; ma++) {
#pragma unroll
        for (int half = 0; half < 2; half++) {
            int row = rowBase + ma * 16 + g + half * 8;
            if (QKV_EPI) {
                int b = row >> 10, srow = row & 1023;
#pragma unroll
                for (int nn = 0; nn < 8; nn++) {
                    int col = colBase + warp * 64 + nn * 8 + 2 * tq;
                    float v0 = acc[ma][nn][half * 2 + 0] + bias[col];
                    float v1 = acc[ma][nn][half * 2 + 1] + bias[col + 1];
                    int which = col / DIM;
                    int rem = col - which * DIM;
                    int h = rem >> 6, d = rem & 63;
                    size_t idx = (((size_t)(b * HEADS + h)) * SEQ + srow) * HDIM + d;
                    if (which == 0) {         // Q: pair
                        uint32_t hi, lo;
                        split2(v0, v1, hi, lo);
                        *(uint32_t*)(g_q_hi + idx) = hi;
                        *(uint32_t*)(g_q_lo + idx) = lo;
                    } else if (which == 1) {  // K: single
                        *(uint32_t*)(g_k_hi + idx) = pack2h(v0, v1);
                    } else {                  // V: single
                        *(uint32_t*)(g_v_hi + idx) = pack2h(v0, v1);
                    }
                }
            } else {
#pragma unroll
                for (int nn = 0; nn < 8; nn++) {
                    int col = colBase + warp * 64 + nn * 8 + 2 * tq;
                    float2 o;
                    o.x = acc[ma][nn][half * 2 + 0] + bias[col];
                    o.y = acc[ma][nn][half * 2 + 1] + bias[col + 1];
                    *(float2*)(out + (size_t)row * DIM + col) = o;
                }
            }
        }
    }
}

// ===========================================================================
// Flash attention: Br=64, 4 warps, 2 CTAs/SM, cp.async 2-stage KV.
// Q/P as fp16 pairs; K/V single fp16.
// ===========================================================================
#define QPITCH 72
#define Q_PL (64*QPITCH)                  // 4608 elems per plane
#define KV_STG (2*Q_PL)                   // K hi + V hi per stage
#define AT_SMEM_BYTES ((2*Q_PL + 2*KV_STG) * 2)   // 55296 bytes

__global__ __launch_bounds__(128, 2) void attn_kernel()
{
    extern __shared__ __half smb[];
    const int tid = threadIdx.x, lane = tid & 31, warp = tid >> 5;
    const int bh = blockIdx.y, qt = blockIdx.x;
    const int g = lane >> 2, t = lane & 3;
    const float scale = 0.125f;

    const size_t base = (size_t)bh * SEQ * HDIM;
    const __half* qh = g_q_hi + base; const __half* ql = g_q_lo + base;
    const __half* kh = g_k_hi + base;
    const __half* vh = g_v_hi + base;

    __half* Qs_hi = smb;
    __half* Qs_lo = smb + Q_PL;

#pragma unroll
    for (int i = 0; i < 4; i++) {
        int id = tid + i * 128;
        int r = id >> 3, c8 = (id & 7) * 8;
        size_t s = (size_t)(qt * 64 + r) * HDIM + c8;
        cp16(smem_u32(Qs_hi + r * QPITCH + c8), qh + s);
        cp16(smem_u32(Qs_lo + r * QPITCH + c8), ql + s);
    }

    auto issue_kv = [&](int kt) {
        if (kt < SEQ / 64) {
            __half* sb = smb + 2 * Q_PL + (kt & 1) * KV_STG;
#pragma unroll
            for (int i = 0; i < 4; i++) {
                int id = tid + i * 128;
                int r = id >> 3, c8 = (id & 7) * 8;
                int doff = r * QPITCH + c8;
                size_t s = (size_t)(kt * 64 + r) * HDIM + c8;
                cp16(smem_u32(sb + doff),        kh + s);
                cp16(smem_u32(sb + Q_PL + doff), vh + s);
            }
        }
        CP_COMMIT();
    };

    issue_kv(0);
    issue_kv(1);

    CP_WAIT1();
    __syncthreads();

    const int a_row = warp * 16 + (lane & 7) + 8 * ((lane >> 3) & 1);
    const int a_col = 8 * (lane >> 4);
    uint32_t qfh[4][4], qfl[4][4];
#pragma unroll
    for (int ka = 0; ka < 4; ka++) {
        int off = a_row * QPITCH + ka * 16 + a_col;
        ldsm4(qfh[ka], smem_u32(&Qs_hi[off]));
        ldsm4(qfl[ka], smem_u32(&Qs_lo[off]));
    }

    const int k_row = (lane & 7) + 8 * (lane >> 4);
    const int k_col = 8 * ((lane >> 3) & 1);
    const int v_row = (lane & 7) + 8 * ((lane >> 3) & 1);
    const int v_col = 8 * (lane >> 4);

    float m0 = -1e30f, m1 = -1e30f, l0 = 0.f, l1 = 0.f;
    float o[8][4];
#pragma unroll
    for (int j = 0; j < 8; j++)
#pragma unroll
        for (int e = 0; e < 4; e++) o[j][e] = 0.f;

    for (int kt = 0; kt < SEQ / 64; kt++) {
        const __half* sb = smb + 2 * Q_PL + (kt & 1) * KV_STG;
        const __half* Ksh = sb;
        const __half* Vsh = sb + Q_PL;

        // ---- S = (Qh+Ql) Kh^T ----
        float s[8][4];
#pragma unroll
        for (int j = 0; j < 8; j++)
#pragma unroll
            for (int e = 0; e < 4; e++) s[j][e] = 0.f;

#pragma unroll
        for (int nb = 0; nb < 4; nb++) {
#pragma unroll
            for (int ka = 0; ka < 4; ka++) {
                int off = (nb * 16 + k_row) * QPITCH + ka * 16 + k_col;
                uint32_t kfh[4];
                ldsm4(kfh, smem_u32(Ksh + off));
                mma16816(s[2*nb],   qfh[ka], &kfh[0]);
                mma16816(s[2*nb+1], qfh[ka], &kfh[2]);
                mma16816(s[2*nb],   qfl[ka], &kfh[0]);
                mma16816(s[2*nb+1], qfl[ka], &kfh[2]);
            }
        }

        // ---- online softmax ----
        float mx0 = -1e30f, mx1 = -1e30f;
#pragma unroll
        for (int j = 0; j < 8; j++) {
            s[j][0] *= scale; s[j][1] *= scale; s[j][2] *= scale; s[j][3] *= scale;
            mx0 = fmaxf(mx0, fmaxf(s[j][0], s[j][1]));
            mx1 = fmaxf(mx1, fmaxf(s[j][2], s[j][3]));
        }
        mx0 = fmaxf(mx0, __shfl_xor_sync(0xffffffffu, mx0, 1));
        mx0 = fmaxf(mx0, __shfl_xor_sync(0xffffffffu, mx0, 2));
        mx1 = fmaxf(mx1, __shfl_xor_sync(0xffffffffu, mx1, 1));
        mx1 = fmaxf(mx1, __shfl_xor_sync(0xffffffffu, mx1, 2));
        float mn0 = fmaxf(m0, mx0), mn1 = fmaxf(m1, mx1);
        float c0 = __expf(m0 - mn0), c1 = __expf(m1 - mn1);
        float p[8][4];
        float ls0 = 0.f, ls1 = 0.f;
#pragma unroll
        for (int j = 0; j < 8; j++) {
            p[j][0] = __expf(s[j][0] - mn0); p[j][1] = __expf(s[j][1] - mn0);
            p[j][2] = __expf(s[j][2] - mn1); p[j][3] = __expf(s[j][3] - mn1);
            ls0 += p[j][0] + p[j][1];
            ls1 += p[j][2] + p[j][3];
        }
        ls0 += __shfl_xor_sync(0xffffffffu, ls0, 1);
        ls0 += __shfl_xor_sync(0xffffffffu, ls0, 2);
        ls1 += __shfl_xor_sync(0xffffffffu, ls1, 1);
        ls1 += __shfl_xor_sync(0xffffffffu, ls1, 2);
        l0 = l0 * c0 + ls0; m0 = mn0;
        l1 = l1 * c1 + ls1; m1 = mn1;
#pragma unroll
        for (int j = 0; j < 8; j++) {
            o[j][0] *= c0; o[j][1] *= c0; o[j][2] *= c1; o[j][3] *= c1;
        }

        // ---- P fragments (fp16 pair) ----
        uint32_t pfh[4][4], pfl[4][4];
#pragma unroll
        for (int ka = 0; ka < 4; ka++) {
            split2(p[2*ka][0],   p[2*ka][1],   pfh[ka][0], pfl[ka][0]);
            split2(p[2*ka][2],   p[2*ka][3],   pfh[ka][1], pfl[ka][1]);
            split2(p[2*ka+1][0], p[2*ka+1][1], pfh[ka][2], pfl[ka][2]);
            split2(p[2*ka+1][2], p[2*ka+1][3], pfh[ka][3], pfl[ka][3]);
        }

        // ---- O += (Ph+Pl) Vh ----
#pragma unroll
        for (int nb = 0; nb < 4; nb++) {
#pragma unroll
            for (int ka = 0; ka < 4; ka++) {
                int off = (ka * 16 + v_row) * QPITCH + nb * 16 + v_col;
                uint32_t vfh[4];
                ldsm4t(vfh, smem_u32(Vsh + off));
                mma16816(o[2*nb],   pfh[ka], &vfh[0]);
                mma16816(o[2*nb+1], pfh[ka], &vfh[2]);
                mma16816(o[2*nb],   pfl[ka], &vfh[0]);
                mma16816(o[2*nb+1], pfl[ka], &vfh[2]);
            }
        }

        __syncthreads();
        issue_kv(kt + 2);
        CP_WAIT1();
        __syncthreads();
    }

    // ---- normalize + write O as fp16 pair into [B,S,D] planes ----
    float i0 = 1.f / l0, i1 = 1.f / l1;
    int b = bh / HEADS, h = bh - (bh / HEADS) * HEADS;
    int srow0 = qt * 64 + warp * 16 + g;
    int srow1 = srow0 + 8;
#pragma unroll
    for (int j = 0; j < 8; j++) {
        int col = h * HDIM + j * 8 + 2 * t;
        size_t i0x = ((size_t)(b * SEQ) + srow0) * DIM + col;
        size_t i1x = ((size_t)(b * SEQ) + srow1) * DIM + col;
        uint32_t hi, lo;
        split2(o[j][0] * i0, o[j][1] * i0, hi, lo);
        *(uint32_t*)(g_o_hi + i0x) = hi;
        *(uint32_t*)(g_o_lo + i0x) = lo;
        split2(o[j][2] * i1, o[j][3] * i1, hi, lo);
        *(uint32_t*)(g_o_hi + i1x) = hi;
        *(uint32_t*)(g_o_lo + i1x) = lo;
    }
}

// ===========================================================================
extern "C" void kernel_launch(void* const* d_in, const int* in_sizes, int n_in,
                              void* d_out, int out_size) {
    const float* x      = (const float*)d_in[0];
    const float* w_qkv  = (const float*)d_in[1];
    const float* b_qkv  = (const float*)d_in[2];
    const float* w_proj = (const float*)d_in[3];
    const float* b_proj = (const float*)d_in[4];
    float* out = (float*)d_out;

    cudaFuncSetAttribute(attn_kernel, cudaFuncAttributeMaxDynamicSharedMemorySize,
                         AT_SMEM_BYTES);
    cudaFuncSetAttribute(mma_gemm_kernel<true>, cudaFuncAttributeMaxDynamicSharedMemorySize,
                         GEMM_SMEM_B);
    cudaFuncSetAttribute(mma_gemm_kernel<false>, cudaFuncAttributeMaxDynamicSharedMemorySize,
                         GEMM_SMEM_B);

    // prep
    split_x_kernel<<<M_ROWS * DIM / 1024, 256>>>(x);
    tsplit_kernel<0><<<dim3(N_QKV / 32, DIM / 32), 256>>>(w_qkv, DIM, N_QKV);
    tsplit_kernel<1><<<dim3(DIM / 32, DIM / 32), 256>>>(w_proj, DIM, DIM);

    // QKV GEMM: M=8192, N=2304
    mma_gemm_kernel<true><<<dim3(N_QKV / 256, M_ROWS / 64), 128, GEMM_SMEM_B>>>(
        b_qkv, nullptr);

    // attention
    attn_kernel<<<dim3(SEQ / 64, BATCH * HEADS), 128, AT_SMEM_BYTES>>>();

    // proj GEMM: M=8192, N=768
    mma_gemm_kernel<false><<<dim3(DIM / 256, M_ROWS / 64), 128, GEMM_SMEM_B>>>(
        b_proj, out);
}

// round 12
// speedup vs baseline: 1.0598x; 1.0598x over previous
#include <cuda_runtime.h>
#include <cuda_bf16.h>
#include <math.h>
#include <stdint.h>

#define BATCH 8
#define SEQ   1024
#define DIM   768
#define HEADS 12
#define HDIM  64
#define M_ROWS (BATCH*SEQ)        // 8192
#define N_QKV  (3*DIM)            // 2304
#define NKT    (DIM/32)           // 24 k-tiles of 32

#define DINLINE __device__ __forceinline__

// ---------------- scratch planes (device-code references ONLY) ----------------
#define QKV_ELEMS (BATCH*HEADS*SEQ*HDIM)
__device__ __nv_bfloat16 g_q_hi[QKV_ELEMS], g_q_lo[QKV_ELEMS];
__device__ __nv_bfloat16 g_k_hi[QKV_ELEMS], g_k_lo[QKV_ELEMS];
__device__ __nv_bfloat16 g_v_hi[QKV_ELEMS], g_v_lo[QKV_ELEMS];
__device__ __nv_bfloat16 g_o_hi[M_ROWS*DIM], g_o_lo[M_ROWS*DIM];
__device__ __nv_bfloat16 g_x_hi[M_ROWS*DIM], g_x_lo[M_ROWS*DIM];     // x split, K-major
__device__ __nv_bfloat16 g_wq_hi[N_QKV*DIM], g_wq_lo[N_QKV*DIM];     // w_qkv^T [N][K]
__device__ __nv_bfloat16 g_wp_hi[DIM*DIM],  g_wp_lo[DIM*DIM];        // w_proj^T [N][K]

// ---------------- PTX helpers ----------------
DINLINE uint32_t smem_u32(const void* p) { return (uint32_t)__cvta_generic_to_shared(p); }

DINLINE void ldsm4(uint32_t r[4], uint32_t a) {
    asm volatile("ldmatrix.sync.aligned.m8n8.x4.shared.b16 {%0,%1,%2,%3},[%4];"
                 : "=r"(r[0]), "=r"(r[1]), "=r"(r[2]), "=r"(r[3]) : "r"(a));
}
DINLINE void ldsm4t(uint32_t r[4], uint32_t a) {
    asm volatile("ldmatrix.sync.aligned.m8n8.x4.trans.shared.b16 {%0,%1,%2,%3},[%4];"
                 : "=r"(r[0]), "=r"(r[1]), "=r"(r[2]), "=r"(r[3]) : "r"(a));
}
DINLINE void mma16816(float c[4], const uint32_t a[4], const uint32_t b[2]) {
    asm volatile("mma.sync.aligned.m16n8k16.row.col.f32.bf16.bf16.f32 "
                 "{%0,%1,%2,%3},{%4,%5,%6,%7},{%8,%9},{%0,%1,%2,%3};"
                 : "+f"(c[0]), "+f"(c[1]), "+f"(c[2]), "+f"(c[3])
                 : "r"(a[0]), "r"(a[1]), "r"(a[2]), "r"(a[3]), "r"(b[0]), "r"(b[1]));
}
DINLINE void cp16(uint32_t dst, const void* src) {
    asm volatile("cp.async.cg.shared.global [%0], [%1], 16;" :: "r"(dst), "l"(src) : "memory");
}
#define CP_COMMIT() asm volatile("cp.async.commit_group;" ::: "memory")
#define CP_WAIT1()  asm volatile("cp.async.wait_group 1;" ::: "memory")

// split fp32 pair into packed bf16 hi/lo
DINLINE void split2(float x, float y, uint32_t &hi, uint32_t &lo) {
    __nv_bfloat16 hx = __float2bfloat16(x);
    __nv_bfloat16 hy = __float2bfloat16(y);
    float rx = x - __bfloat162float(hx);
    float ry = y - __bfloat162float(hy);
    __nv_bfloat162 h2; h2.x = hx; h2.y = hy;
    __nv_bfloat162 l2; l2.x = __float2bfloat16(rx); l2.y = __float2bfloat16(ry);
    hi = *reinterpret_cast<uint32_t*>(&h2);
    lo = *reinterpret_cast<uint32_t*>(&l2);
}

// ===========================================================================
// Prep kernels
// ===========================================================================
__global__ __launch_bounds__(256) void split_x_kernel(const float* __restrict__ x) {
    int i = blockIdx.x * 256 + threadIdx.x;   // one float4
    float4 v = ((const float4*)x)[i];
    uint32_t h0, l0, h1, l1;
    split2(v.x, v.y, h0, l0);
    split2(v.z, v.w, h1, l1);
    ((uint2*)g_x_hi)[i] = make_uint2(h0, h1);
    ((uint2*)g_x_lo)[i] = make_uint2(l0, l1);
}

// src [K][N] fp32 -> plane set WSEL (0: w_qkv->g_wq, 1: w_proj->g_wp), [N][K] bf16 hi/lo
template <int WSEL>
__global__ __launch_bounds__(256) void tsplit_kernel(
    const float* __restrict__ src, int K, int N)
{
    __nv_bfloat16* dh = (WSEL == 0) ? g_wq_hi : g_wp_hi;
    __nv_bfloat16* dl = (WSEL == 0) ? g_wq_lo : g_wp_lo;
    __shared__ float T[32][33];
    int k0 = blockIdx.y * 32, n0 = blockIdx.x * 32;
    int tx = threadIdx.x & 31, ty = threadIdx.x >> 5;
#pragma unroll
    for (int i = 0; i < 4; i++)
        T[ty + 8 * i][tx] = src[(size_t)(k0 + ty + 8 * i) * N + n0 + tx];
    __syncthreads();
#pragma unroll
    for (int i = 0; i < 4; i++) {
        float v = T[tx][ty + 8 * i];
        __nv_bfloat16 h = __float2bfloat16(v);
        size_t o = (size_t)(n0 + ty + 8 * i) * K + k0 + tx;
        dh[o] = h;
        dl[o] = __float2bfloat16(v - __bfloat162float(h));
    }
}

// ===========================================================================
// bf16x3 mma.sync GEMM. Block 64x256, 4 warps, warp tile 64x64.
// BK=32, 2-stage cp.async pipeline, 2 CTAs/SM.
// R12: A-frags loaded once per k-tile; B-frags double-buffered prefetch.
// ===========================================================================
#define PAe 40                       // smem pitch in bf16 elems (80B): conflict-free
#define A_STG (64*PAe)               // elems per A plane per stage
#define B_STG (256*PAe)
#define STG_ELEMS (2*A_STG + 2*B_STG)          // 25600 elems
#define GEMM_SMEM_B (2 * STG_ELEMS * 2)        // 102400 bytes

template <bool QKV_EPI>
__global__ __launch_bounds__(128, 2) void mma_gemm_kernel(
    const float* __restrict__ bias, float* __restrict__ out)
{
    const __nv_bfloat16* Ah = QKV_EPI ? g_x_hi : g_o_hi;
    const __nv_bfloat16* Al = QKV_EPI ? g_x_lo : g_o_lo;
    const __nv_bfloat16* Bh = QKV_EPI ? g_wq_hi : g_wp_hi;
    const __nv_bfloat16* Bl = QKV_EPI ? g_wq_lo : g_wp_lo;

    extern __shared__ __nv_bfloat16 sm[];
    const int tid = threadIdx.x, lane = tid & 31, warp = tid >> 5;
    const int rowBase = blockIdx.y * 64, colBase = blockIdx.x * 256;

    float acc[4][8][4];
#pragma unroll
    for (int i = 0; i < 4; i++)
#pragma unroll
        for (int j = 0; j < 8; j++)
#pragma unroll
            for (int e = 0; e < 4; e++) acc[i][j][e] = 0.f;

    auto issue = [&](int st) {
        if (st < NKT) {
            const int k0 = st * 32;
            __nv_bfloat16* base = sm + (st & 1) * STG_ELEMS;
#pragma unroll
            for (int i = 0; i < 2; i++) {
                int id = tid + i * 128;
                int r = id >> 2, c8 = (id & 3) * 8;
                uint32_t d = smem_u32(base + r * PAe + c8);
                size_t s = (size_t)(rowBase + r) * DIM + k0 + c8;
                cp16(d, Ah + s);
                cp16(d + A_STG * 2, Al + s);
            }
#pragma unroll
            for (int i = 0; i < 8; i++) {
                int id = tid + i * 128;
                int r = id >> 2, c8 = (id & 3) * 8;
                uint32_t d = smem_u32(base + 2 * A_STG + r * PAe + c8);
                size_t s = (size_t)(colBase + r) * DIM + k0 + c8;
                cp16(d, Bh + s);
                cp16(d + B_STG * 2, Bl + s);
            }
        }
        CP_COMMIT();
    };

    issue(0);
    issue(1);

    const int a_ro = (lane & 7) + 8 * ((lane >> 3) & 1);
    const int a_co = 8 * (lane >> 4);
    const int b_ro = (lane & 7) + 8 * (lane >> 4);
    const int b_co = 8 * ((lane >> 3) & 1);

    for (int t = 0; t < NKT; t++) {
        CP_WAIT1();
        __syncthreads();
        const __nv_bfloat16* stg = sm + (t & 1) * STG_ELEMS;
        const __nv_bfloat16* sAh = stg;
        const __nv_bfloat16* sAl = stg + A_STG;
        const __nv_bfloat16* sBh = stg + 2 * A_STG;
        const __nv_bfloat16* sBl = stg + 2 * A_STG + B_STG;

        // ---- load ALL A fragments for both k16-steps (16 ldsm, 64 regs) ----
        uint32_t afh[2][4][4], afl[2][4][4];
#pragma unroll
        for (int ks = 0; ks < 2; ks++)
#pragma unroll
            for (int ma = 0; ma < 4; ma++) {
                int off = (ma * 16 + a_ro) * PAe + ks * 16 + a_co;
                ldsm4(afh[ks][ma], smem_u32(sAh + off));
                ldsm4(afl[ks][ma], smem_u32(sAl + off));
            }

        // ---- B fragment double-buffered prefetch over 8 (ks,nb) steps ----
        uint32_t bfh[2][4], bfl[2][4];
        {
            int off0 = (warp * 64 + b_ro) * PAe + b_co;   // ks=0, nb=0
            ldsm4(bfh[0], smem_u32(sBh + off0));
            ldsm4(bfl[0], smem_u32(sBl + off0));
        }
#pragma unroll
        for (int step = 0; step < 8; step++) {
            const int ks = step >> 2, nb = step & 3;
            const int cur = step & 1, nxt = cur ^ 1;
            if (step < 7) {
                const int s2 = step + 1;
                const int ks2 = s2 >> 2, nb2 = s2 & 3;
                int off = (warp * 64 + nb2 * 16 + b_ro) * PAe + ks2 * 16 + b_co;
                ldsm4(bfh[nxt], smem_u32(sBh + off));
                ldsm4(bfl[nxt], smem_u32(sBl + off));
            }
#pragma unroll
            for (int ma = 0; ma < 4; ma++) {
                mma16816(acc[ma][2*nb],   afh[ks][ma], &bfh[cur][0]);
                mma16816(acc[ma][2*nb+1], afh[ks][ma], &bfh[cur][2]);
                mma16816(acc[ma][2*nb],   afh[ks][ma], &bfl[cur][0]);
                mma16816(acc[ma][2*nb+1], afh[ks][ma], &bfl[cur][2]);
                mma16816(acc[ma][2*nb],   afl[ks][ma], &bfh[cur][0]);
                mma16816(acc[ma][2*nb+1], afl[ks][ma], &bfh[cur][2]);
            }
        }
        __syncthreads();
        issue(t + 2);
    }

    // ---------------- epilogue ----------------
    const int g = lane >> 2, tq = lane & 3;
#pragma unroll
    for (int ma = 0; ma < 4; ma++) {
#pragma unroll
        for (int half = 0; half < 2; half++) {
            int row = rowBase + ma * 16 + g + half * 8;
            if (QKV_EPI) {
                int b = row >> 10, srow = row & 1023;
#pragma unroll
                for (int nn = 0; nn < 8; nn++) {
                    int col = colBase + warp * 64 + nn * 8 + 2 * tq;
                    float v0 = acc[ma][nn][half * 2 + 0] + bias[col];
                    float v1 = acc[ma][nn][half * 2 + 1] + bias[col + 1];
                    int which = col / DIM;
                    int rem = col - which * DIM;
                    int h = rem >> 6, d = rem & 63;
                    size_t idx = (((size_t)(b * HEADS + h)) * SEQ + srow) * HDIM + d;
                    __nv_bfloat16* dh = (which == 0) ? g_q_hi : (which == 1) ? g_k_hi : g_v_hi;
                    __nv_bfloat16* dl = (which == 0) ? g_q_lo : (which == 1) ? g_k_lo : g_v_lo;
                    uint32_t hi, lo;
                    split2(v0, v1, hi, lo);
                    *(uint32_t*)(dh + idx) = hi;
                    *(uint32_t*)(dl + idx) = lo;
                }
            } else {
#pragma unroll
                for (int nn = 0; nn < 8; nn++) {
                    int col = colBase + warp * 64 + nn * 8 + 2 * tq;
                    float2 o;
                    o.x = acc[ma][nn][half * 2 + 0] + bias[col];
                    o.y = acc[ma][nn][half * 2 + 1] + bias[col + 1];
                    *(float2*)(out + (size_t)row * DIM + col) = o;
                }
            }
        }
    }
}

// ===========================================================================
// Flash attention (R10/R8 config — best measured).
// Br=64, 4 warps, 2 CTAs/SM, cp.async 2-stage KV.
// ===========================================================================
#define QPITCH 72
#define Q_PL (64*QPITCH)
#define KV_STG (4*Q_PL)
#define AT_SMEM_BYTES ((2*Q_PL + 2*KV_STG) * 2)   // 92160 bytes

__global__ __launch_bounds__(128, 2) void attn_kernel()
{
    extern __shared__ __nv_bfloat16 smb[];
    const int tid = threadIdx.x, lane = tid & 31, warp = tid >> 5;
    const int bh = blockIdx.y, qt = blockIdx.x;
    const int g = lane >> 2, t = lane & 3;
    const float scale = 0.125f;

    const size_t base = (size_t)bh * SEQ * HDIM;
    const __nv_bfloat16* qh = g_q_hi + base; const __nv_bfloat16* ql = g_q_lo + base;
    const __nv_bfloat16* kh = g_k_hi + base; const __nv_bfloat16* kl = g_k_lo + base;
    const __nv_bfloat16* vh = g_v_hi + base; const __nv_bfloat16* vl = g_v_lo + base;

    __nv_bfloat16* Qs_hi = smb;
    __nv_bfloat16* Qs_lo = smb + Q_PL;

#pragma unroll
    for (int i = 0; i < 4; i++) {
        int id = tid + i * 128;
        int r = id >> 3, c8 = (id & 7) * 8;
        size_t s = (size_t)(qt * 64 + r) * HDIM + c8;
        cp16(smem_u32(Qs_hi + r * QPITCH + c8), qh + s);
        cp16(smem_u32(Qs_lo + r * QPITCH + c8), ql + s);
    }

    auto issue_kv = [&](int kt) {
        if (kt < SEQ / 64) {
            __nv_bfloat16* sb = smb + 2 * Q_PL + (kt & 1) * KV_STG;
#pragma unroll
            for (int i = 0; i < 4; i++) {
                int id = tid + i * 128;
                int r = id >> 3, c8 = (id & 7) * 8;
                int doff = r * QPITCH + c8;
                size_t s = (size_t)(kt * 64 + r) * HDIM + c8;
                cp16(smem_u32(sb + doff),            kh + s);
                cp16(smem_u32(sb + Q_PL + doff),     kl + s);
                cp16(smem_u32(sb + 2 * Q_PL + doff), vh + s);
                cp16(smem_u32(sb + 3 * Q_PL + doff), vl + s);
            }
        }
        CP_COMMIT();
    };

    issue_kv(0);
    issue_kv(1);

    CP_WAIT1();
    __syncthreads();

    const int a_row = warp * 16 + (lane & 7) + 8 * ((lane >> 3) & 1);
    const int a_col = 8 * (lane >> 4);
    uint32_t qfh[4][4], qfl[4][4];
#pragma unroll
    for (int ka = 0; ka < 4; ka++) {
        int off = a_row * QPITCH + ka * 16 + a_col;
        ldsm4(qfh[ka], smem_u32(&Qs_hi[off]));
        ldsm4(qfl[ka], smem_u32(&Qs_lo[off]));
    }

    const int k_row = (lane & 7) + 8 * (lane >> 4);
    const int k_col = 8 * ((lane >> 3) & 1);
    const int v_row = (lane & 7) + 8 * ((lane >> 3) & 1);
    const int v_col = 8 * (lane >> 4);

    float m0 = -1e30f, m1 = -1e30f, l0 = 0.f, l1 = 0.f;
    float o[8][4];
#pragma unroll
    for (int j = 0; j < 8; j++)
#pragma unroll
        for (int e = 0; e < 4; e++) o[j][e] = 0.f;

    for (int kt = 0; kt < SEQ / 64; kt++) {
        const __nv_bfloat16* sb = smb + 2 * Q_PL + (kt & 1) * KV_STG;
        const __nv_bfloat16* Ksh = sb;
        const __nv_bfloat16* Ksl = sb + Q_PL;
        const __nv_bfloat16* Vsh = sb + 2 * Q_PL;
        const __nv_bfloat16* Vsl = sb + 3 * Q_PL;

        float s[8][4];
#pragma unroll
        for (int j = 0; j < 8; j++)
#pragma unroll
            for (int e = 0; e < 4; e++) s[j][e] = 0.f;

#pragma unroll
        for (int nb = 0; nb < 4; nb++) {
#pragma unroll
            for (int ka = 0; ka < 4; ka++) {
                int off = (nb * 16 + k_row) * QPITCH + ka * 16 + k_col;
                uint32_t kfh[4], kfl[4];
                ldsm4(kfh, smem_u32(Ksh + off));
                ldsm4(kfl, smem_u32(Ksl + off));
                mma16816(s[2*nb],   qfh[ka], &kfh[0]);
                mma16816(s[2*nb+1], qfh[ka], &kfh[2]);
                mma16816(s[2*nb],   qfh[ka], &kfl[0]);
                mma16816(s[2*nb+1], qfh[ka], &kfl[2]);
                mma16816(s[2*nb],   qfl[ka], &kfh[0]);
                mma16816(s[2*nb+1], qfl[ka], &kfh[2]);
            }
        }

        float mx0 = -1e30f, mx1 = -1e30f;
#pragma unroll
        for (int j = 0; j < 8; j++) {
            s[j][0] *= scale; s[j][1] *= scale; s[j][2] *= scale; s[j][3] *= scale;
            mx0 = fmaxf(mx0, fmaxf(s[j][0], s[j][1]));
            mx1 = fmaxf(mx1, fmaxf(s[j][2], s[j][3]));
        }
        mx0 = fmaxf(mx0, __shfl_xor_sync(0xffffffffu, mx0, 1));
        mx0 = fmaxf(mx0, __shfl_xor_sync(0xffffffffu, mx0, 2));
        mx1 = fmaxf(mx1, __shfl_xor_sync(0xffffffffu, mx1, 1));
        mx1 = fmaxf(mx1, __shfl_xor_sync(0xffffffffu, mx1, 2));
        float mn0 = fmaxf(m0, mx0), mn1 = fmaxf(m1, mx1);
        float c0 = __expf(m0 - mn0), c1 = __expf(m1 - mn1);
        float p[8][4];
        float ls0 = 0.f, ls1 = 0.f;
#pragma unroll
        for (int j = 0; j < 8; j++) {
            p[j][0] = __expf(s[j][0] - mn0); p[j][1] = __expf(s[j][1] - mn0);
            p[j][2] = __expf(s[j][2] - mn1); p[j][3] = __expf(s[j][3] - mn1);
            ls0 += p[j][0] + p[j][1];
            ls1 += p[j][2] + p[j][3];
        }
        ls0 += __shfl_xor_sync(0xffffffffu, ls0, 1);
        ls0 += __shfl_xor_sync(0xffffffffu, ls0, 2);
        ls1 += __shfl_xor_sync(0xffffffffu, ls1, 1);
        ls1 += __shfl_xor_sync(0xffffffffu, ls1, 2);
        l0 = l0 * c0 + ls0; m0 = mn0;
        l1 = l1 * c1 + ls1; m1 = mn1;
#pragma unroll
        for (int j = 0; j < 8; j++) {
            o[j][0] *= c0; o[j][1] *= c0; o[j][2] *= c1; o[j][3] *= c1;
        }

        uint32_t pfh[4][4], pfl[4][4];
#pragma unroll
        for (int ka = 0; ka < 4; ka++) {
            split2(p[2*ka][0],   p[2*ka][1],   pfh[ka][0], pfl[ka][0]);
            split2(p[2*ka][2],   p[2*ka][3],   pfh[ka][1], pfl[ka][1]);
            split2(p[2*ka+1][0], p[2*ka+1][1], pfh[ka][2], pfl[ka][2]);
            split2(p[2*ka+1][2], p[2*ka+1][3], pfh[ka][3], pfl[ka][3]);
        }

#pragma unroll
        for (int nb = 0; nb < 4; nb++) {
#pragma unroll
            for (int ka = 0; ka < 4; ka++) {
                int off = (ka * 16 + v_row) * QPITCH + nb * 16 + v_col;
                uint32_t vfh[4], vfl[4];
                ldsm4t(vfh, smem_u32(Vsh + off));
                ldsm4t(vfl, smem_u32(Vsl + off));
                mma16816(o[2*nb],   pfh[ka], &vfh[0]);
                mma16816(o[2*nb+1], pfh[ka], &vfh[2]);
                mma16816(o[2*nb],   pfh[ka], &vfl[0]);
                mma16816(o[2*nb+1], pfh[ka], &vfl[2]);
                mma16816(o[2*nb],   pfl[ka], &vfh[0]);
                mma16816(o[2*nb+1], pfl[ka], &vfh[2]);
            }
        }

        __syncthreads();
        issue_kv(kt + 2);
        CP_WAIT1();
        __syncthreads();
    }

    float i0 = 1.f / l0, i1 = 1.f / l1;
    int b = bh / HEADS, h = bh - (bh / HEADS) * HEADS;
    int srow0 = qt * 64 + warp * 16 + g;
    int srow1 = srow0 + 8;
#pragma unroll
    for (int j = 0; j < 8; j++) {
        int col = h * HDIM + j * 8 + 2 * t;
        size_t i0x = ((size_t)(b * SEQ) + srow0) * DIM + col;
        size_t i1x = ((size_t)(b * SEQ) + srow1) * DIM + col;
        uint32_t hi, lo;
        split2(o[j][0] * i0, o[j][1] * i0, hi, lo);
        *(uint32_t*)(g_o_hi + i0x) = hi;
        *(uint32_t*)(g_o_lo + i0x) = lo;
        split2(o[j][2] * i1, o[j][3] * i1, hi, lo);
        *(uint32_t*)(g_o_hi + i1x) = hi;
        *(uint32_t*)(g_o_lo + i1x) = lo;
    }
}

// ===========================================================================
extern "C" void kernel_launch(void* const* d_in, const int* in_sizes, int n_in,
                              void* d_out, int out_size) {
    const float* x      = (const float*)d_in[0];
    const float* w_qkv  = (const float*)d_in[1];
    const float* b_qkv  = (const float*)d_in[2];
    const float* w_proj = (const float*)d_in[3];
    const float* b_proj = (const float*)d_in[4];
    float* out = (float*)d_out;

    cudaFuncSetAttribute(attn_kernel, cudaFuncAttributeMaxDynamicSharedMemorySize,
                         AT_SMEM_BYTES);
    cudaFuncSetAttribute(mma_gemm_kernel<true>, cudaFuncAttributeMaxDynamicSharedMemorySize,
                         GEMM_SMEM_B);
    cudaFuncSetAttribute(mma_gemm_kernel<false>, cudaFuncAttributeMaxDynamicSharedMemorySize,
                         GEMM_SMEM_B);

    // prep
    split_x_kernel<<<M_ROWS * DIM / 1024, 256>>>(x);
    tsplit_kernel<0><<<dim3(N_QKV / 32, DIM / 32), 256>>>(w_qkv, DIM, N_QKV);
    tsplit_kernel<1><<<dim3(DIM / 32, DIM / 32), 256>>>(w_proj, DIM, DIM);

    // QKV GEMM: M=8192, N=2304
    mma_gemm_kernel<true><<<dim3(N_QKV / 256, M_ROWS / 64), 128, GEMM_SMEM_B>>>(
        b_qkv, nullptr);

    // attention
    attn_kernel<<<dim3(SEQ / 64, BATCH * HEADS), 128, AT_SMEM_BYTES>>>();

    // proj GEMM: M=8192, N=768
    mma_gemm_kernel<false><<<dim3(DIM / 256, M_ROWS / 64), 128, GEMM_SMEM_B>>>(
        b_proj, out);
}

// round 13
// speedup vs baseline: 1.0600x; 1.0001x over previous
#include <cuda_runtime.h>
#include <cuda_bf16.h>
#include <math.h>
#include <stdint.h>

#define BATCH 8
#define SEQ   1024
#define DIM   768
#define HEADS 12
#define HDIM  64
#define M_ROWS (BATCH*SEQ)        // 8192
#define N_QKV  (3*DIM)            // 2304
#define NKT    (DIM/32)           // 24 k-tiles of 32

#define DINLINE __device__ __forceinline__

// ---------------- scratch planes (device-code references ONLY) ----------------
#define QKV_ELEMS (BATCH*HEADS*SEQ*HDIM)
__device__ __nv_bfloat16 g_q_hi[QKV_ELEMS], g_q_lo[QKV_ELEMS];
__device__ __nv_bfloat16 g_k_hi[QKV_ELEMS], g_k_lo[QKV_ELEMS];
__device__ __nv_bfloat16 g_v_hi[QKV_ELEMS], g_v_lo[QKV_ELEMS];
__device__ __nv_bfloat16 g_o_hi[M_ROWS*DIM], g_o_lo[M_ROWS*DIM];
__device__ __nv_bfloat16 g_x_hi[M_ROWS*DIM], g_x_lo[M_ROWS*DIM];     // x split, K-major
__device__ __nv_bfloat16 g_wq_hi[N_QKV*DIM], g_wq_lo[N_QKV*DIM];     // w_qkv^T [N][K]
__device__ __nv_bfloat16 g_wp_hi[DIM*DIM],  g_wp_lo[DIM*DIM];        // w_proj^T [N][K]

// ---------------- PTX helpers ----------------
DINLINE uint32_t smem_u32(const void* p) { return (uint32_t)__cvta_generic_to_shared(p); }

DINLINE void ldsm4(uint32_t r[4], uint32_t a) {
    asm volatile("ldmatrix.sync.aligned.m8n8.x4.shared.b16 {%0,%1,%2,%3},[%4];"
                 : "=r"(r[0]), "=r"(r[1]), "=r"(r[2]), "=r"(r[3]) : "r"(a));
}
DINLINE void ldsm4t(uint32_t r[4], uint32_t a) {
    asm volatile("ldmatrix.sync.aligned.m8n8.x4.trans.shared.b16 {%0,%1,%2,%3},[%4];"
                 : "=r"(r[0]), "=r"(r[1]), "=r"(r[2]), "=r"(r[3]) : "r"(a));
}
DINLINE void mma16816(float c[4], const uint32_t a[4], const uint32_t b[2]) {
    asm volatile("mma.sync.aligned.m16n8k16.row.col.f32.bf16.bf16.f32 "
                 "{%0,%1,%2,%3},{%4,%5,%6,%7},{%8,%9},{%0,%1,%2,%3};"
                 : "+f"(c[0]), "+f"(c[1]), "+f"(c[2]), "+f"(c[3])
                 : "r"(a[0]), "r"(a[1]), "r"(a[2]), "r"(a[3]), "r"(b[0]), "r"(b[1]));
}
DINLINE void cp16(uint32_t dst, const void* src) {
    asm volatile("cp.async.cg.shared.global [%0], [%1], 16;" :: "r"(dst), "l"(src) : "memory");
}
#define CP_COMMIT() asm volatile("cp.async.commit_group;" ::: "memory")
#define CP_WAIT1()  asm volatile("cp.async.wait_group 1;" ::: "memory")

// split fp32 pair into packed bf16 hi/lo
DINLINE void split2(float x, float y, uint32_t &hi, uint32_t &lo) {
    __nv_bfloat16 hx = __float2bfloat16(x);
    __nv_bfloat16 hy = __float2bfloat16(y);
    float rx = x - __bfloat162float(hx);
    float ry = y - __bfloat162float(hy);
    __nv_bfloat162 h2; h2.x = hx; h2.y = hy;
    __nv_bfloat162 l2; l2.x = __float2bfloat16(rx); l2.y = __float2bfloat16(ry);
    hi = *reinterpret_cast<uint32_t*>(&h2);
    lo = *reinterpret_cast<uint32_t*>(&l2);
}

// ===========================================================================
// Prep kernels
// ===========================================================================
__global__ __launch_bounds__(256) void split_x_kernel(const float* __restrict__ x) {
    int i = blockIdx.x * 256 + threadIdx.x;   // one float4
    float4 v = ((const float4*)x)[i];
    uint32_t h0, l0, h1, l1;
    split2(v.x, v.y, h0, l0);
    split2(v.z, v.w, h1, l1);
    ((uint2*)g_x_hi)[i] = make_uint2(h0, h1);
    ((uint2*)g_x_lo)[i] = make_uint2(l0, l1);
}

// src [K][N] fp32 -> plane set WSEL (0: w_qkv->g_wq, 1: w_proj->g_wp), [N][K] bf16 hi/lo
template <int WSEL>
__global__ __launch_bounds__(256) void tsplit_kernel(
    const float* __restrict__ src, int K, int N)
{
    __nv_bfloat16* dh = (WSEL == 0) ? g_wq_hi : g_wp_hi;
    __nv_bfloat16* dl = (WSEL == 0) ? g_wq_lo : g_wp_lo;
    __shared__ float T[32][33];
    int k0 = blockIdx.y * 32, n0 = blockIdx.x * 32;
    int tx = threadIdx.x & 31, ty = threadIdx.x >> 5;
#pragma unroll
    for (int i = 0; i < 4; i++)
        T[ty + 8 * i][tx] = src[(size_t)(k0 + ty + 8 * i) * N + n0 + tx];
    __syncthreads();
#pragma unroll
    for (int i = 0; i < 4; i++) {
        float v = T[tx][ty + 8 * i];
        __nv_bfloat16 h = __float2bfloat16(v);
        size_t o = (size_t)(n0 + ty + 8 * i) * K + k0 + tx;
        dh[o] = h;
        dl[o] = __float2bfloat16(v - __bfloat162float(h));
    }
}

// ===========================================================================
// bf16x3 mma.sync GEMM (R12 — best measured). Block 64x256, 4 warps,
// warp tile 64x64, BK=32, 2-stage cp.async, B-fragment prefetch.
// ===========================================================================
#define PAe 40                       // smem pitch in bf16 elems (80B): conflict-free
#define A_STG (64*PAe)               // elems per A plane per stage
#define B_STG (256*PAe)
#define STG_ELEMS (2*A_STG + 2*B_STG)          // 25600 elems
#define GEMM_SMEM_B (2 * STG_ELEMS * 2)        // 102400 bytes

template <bool QKV_EPI>
__global__ __launch_bounds__(128, 2) void mma_gemm_kernel(
    const float* __restrict__ bias, float* __restrict__ out)
{
    const __nv_bfloat16* Ah = QKV_EPI ? g_x_hi : g_o_hi;
    const __nv_bfloat16* Al = QKV_EPI ? g_x_lo : g_o_lo;
    const __nv_bfloat16* Bh = QKV_EPI ? g_wq_hi : g_wp_hi;
    const __nv_bfloat16* Bl = QKV_EPI ? g_wq_lo : g_wp_lo;

    extern __shared__ __nv_bfloat16 sm[];
    const int tid = threadIdx.x, lane = tid & 31, warp = tid >> 5;
    const int rowBase = blockIdx.y * 64, colBase = blockIdx.x * 256;

    float acc[4][8][4];
#pragma unroll
    for (int i = 0; i < 4; i++)
#pragma unroll
        for (int j = 0; j < 8; j++)
#pragma unroll
            for (int e = 0; e < 4; e++) acc[i][j][e] = 0.f;

    auto issue = [&](int st) {
        if (st < NKT) {
            const int k0 = st * 32;
            __nv_bfloat16* base = sm + (st & 1) * STG_ELEMS;
#pragma unroll
            for (int i = 0; i < 2; i++) {
                int id = tid + i * 128;
                int r = id >> 2, c8 = (id & 3) * 8;
                uint32_t d = smem_u32(base + r * PAe + c8);
                size_t s = (size_t)(rowBase + r) * DIM + k0 + c8;
                cp16(d, Ah + s);
                cp16(d + A_STG * 2, Al + s);
            }
#pragma unroll
            for (int i = 0; i < 8; i++) {
                int id = tid + i * 128;
                int r = id >> 2, c8 = (id & 3) * 8;
                uint32_t d = smem_u32(base + 2 * A_STG + r * PAe + c8);
                size_t s = (size_t)(colBase + r) * DIM + k0 + c8;
                cp16(d, Bh + s);
                cp16(d + B_STG * 2, Bl + s);
            }
        }
        CP_COMMIT();
    };

    issue(0);
    issue(1);

    const int a_ro = (lane & 7) + 8 * ((lane >> 3) & 1);
    const int a_co = 8 * (lane >> 4);
    const int b_ro = (lane & 7) + 8 * (lane >> 4);
    const int b_co = 8 * ((lane >> 3) & 1);

    for (int t = 0; t < NKT; t++) {
        CP_WAIT1();
        __syncthreads();
        const __nv_bfloat16* stg = sm + (t & 1) * STG_ELEMS;
        const __nv_bfloat16* sAh = stg;
        const __nv_bfloat16* sAl = stg + A_STG;
        const __nv_bfloat16* sBh = stg + 2 * A_STG;
        const __nv_bfloat16* sBl = stg + 2 * A_STG + B_STG;

        uint32_t afh[2][4][4], afl[2][4][4];
#pragma unroll
        for (int ks = 0; ks < 2; ks++)
#pragma unroll
            for (int ma = 0; ma < 4; ma++) {
                int off = (ma * 16 + a_ro) * PAe + ks * 16 + a_co;
                ldsm4(afh[ks][ma], smem_u32(sAh + off));
                ldsm4(afl[ks][ma], smem_u32(sAl + off));
            }

        uint32_t bfh[2][4], bfl[2][4];
        {
            int off0 = (warp * 64 + b_ro) * PAe + b_co;
            ldsm4(bfh[0], smem_u32(sBh + off0));
            ldsm4(bfl[0], smem_u32(sBl + off0));
        }
#pragma unroll
        for (int step = 0; step < 8; step++) {
            const int ks = step >> 2, nb = step & 3;
            const int cur = step & 1, nxt = cur ^ 1;
            if (step < 7) {
                const int s2 = step + 1;
                const int ks2 = s2 >> 2, nb2 = s2 & 3;
                int off = (warp * 64 + nb2 * 16 + b_ro) * PAe + ks2 * 16 + b_co;
                ldsm4(bfh[nxt], smem_u32(sBh + off));
                ldsm4(bfl[nxt], smem_u32(sBl + off));
            }
#pragma unroll
            for (int ma = 0; ma < 4; ma++) {
                mma16816(acc[ma][2*nb],   afh[ks][ma], &bfh[cur][0]);
                mma16816(acc[ma][2*nb+1], afh[ks][ma], &bfh[cur][2]);
                mma16816(acc[ma][2*nb],   afh[ks][ma], &bfl[cur][0]);
                mma16816(acc[ma][2*nb+1], afh[ks][ma], &bfl[cur][2]);
                mma16816(acc[ma][2*nb],   afl[ks][ma], &bfh[cur][0]);
                mma16816(acc[ma][2*nb+1], afl[ks][ma], &bfh[cur][2]);
            }
        }
        __syncthreads();
        issue(t + 2);
    }

    // ---------------- epilogue ----------------
    const int g = lane >> 2, tq = lane & 3;
#pragma unroll
    for (int ma = 0; ma < 4; ma++) {
#pragma unroll
        for (int half = 0; half < 2; half++) {
            int row = rowBase + ma * 16 + g + half * 8;
            if (QKV_EPI) {
                int b = row >> 10, srow = row & 1023;
#pragma unroll
                for (int nn = 0; nn < 8; nn++) {
                    int col = colBase + warp * 64 + nn * 8 + 2 * tq;
                    float v0 = acc[ma][nn][half * 2 + 0] + bias[col];
                    float v1 = acc[ma][nn][half * 2 + 1] + bias[col + 1];
                    int which = col / DIM;
                    int rem = col - which * DIM;
                    int h = rem >> 6, d = rem & 63;
                    size_t idx = (((size_t)(b * HEADS + h)) * SEQ + srow) * HDIM + d;
                    __nv_bfloat16* dh = (which == 0) ? g_q_hi : (which == 1) ? g_k_hi : g_v_hi;
                    __nv_bfloat16* dl = (which == 0) ? g_q_lo : (which == 1) ? g_k_lo : g_v_lo;
                    uint32_t hi, lo;
                    split2(v0, v1, hi, lo);
                    *(uint32_t*)(dh + idx) = hi;
                    *(uint32_t*)(dl + idx) = lo;
                }
            } else {
#pragma unroll
                for (int nn = 0; nn < 8; nn++) {
                    int col = colBase + warp * 64 + nn * 8 + 2 * tq;
                    float2 o;
                    o.x = acc[ma][nn][half * 2 + 0] + bias[col];
                    o.y = acc[ma][nn][half * 2 + 1] + bias[col + 1];
                    *(float2*)(out + (size_t)row * DIM + col) = o;
                }
            }
        }
    }
}

// ===========================================================================
// Flash attention: Br=64, 4 warps, 2 CTAs/SM, cp.async 2-stage KV.
// R13: K/V fragment double-buffered prefetch in both MMA loops.
// ===========================================================================
#define QPITCH 72
#define Q_PL (64*QPITCH)
#define KV_STG (4*Q_PL)
#define AT_SMEM_BYTES ((2*Q_PL + 2*KV_STG) * 2)   // 92160 bytes

__global__ __launch_bounds__(128, 2) void attn_kernel()
{
    extern __shared__ __nv_bfloat16 smb[];
    const int tid = threadIdx.x, lane = tid & 31, warp = tid >> 5;
    const int bh = blockIdx.y, qt = blockIdx.x;
    const int g = lane >> 2, t = lane & 3;
    const float scale = 0.125f;

    const size_t base = (size_t)bh * SEQ * HDIM;
    const __nv_bfloat16* qh = g_q_hi + base; const __nv_bfloat16* ql = g_q_lo + base;
    const __nv_bfloat16* kh = g_k_hi + base; const __nv_bfloat16* kl = g_k_lo + base;
    const __nv_bfloat16* vh = g_v_hi + base; const __nv_bfloat16* vl = g_v_lo + base;

    __nv_bfloat16* Qs_hi = smb;
    __nv_bfloat16* Qs_lo = smb + Q_PL;

#pragma unroll
    for (int i = 0; i < 4; i++) {
        int id = tid + i * 128;
        int r = id >> 3, c8 = (id & 7) * 8;
        size_t s = (size_t)(qt * 64 + r) * HDIM + c8;
        cp16(smem_u32(Qs_hi + r * QPITCH + c8), qh + s);
        cp16(smem_u32(Qs_lo + r * QPITCH + c8), ql + s);
    }

    auto issue_kv = [&](int kt) {
        if (kt < SEQ / 64) {
            __nv_bfloat16* sb = smb + 2 * Q_PL + (kt & 1) * KV_STG;
#pragma unroll
            for (int i = 0; i < 4; i++) {
                int id = tid + i * 128;
                int r = id >> 3, c8 = (id & 7) * 8;
                int doff = r * QPITCH + c8;
                size_t s = (size_t)(kt * 64 + r) * HDIM + c8;
                cp16(smem_u32(sb + doff),            kh + s);
                cp16(smem_u32(sb + Q_PL + doff),     kl + s);
                cp16(smem_u32(sb + 2 * Q_PL + doff), vh + s);
                cp16(smem_u32(sb + 3 * Q_PL + doff), vl + s);
            }
        }
        CP_COMMIT();
    };

    issue_kv(0);
    issue_kv(1);

    CP_WAIT1();
    __syncthreads();

    const int a_row = warp * 16 + (lane & 7) + 8 * ((lane >> 3) & 1);
    const int a_col = 8 * (lane >> 4);
    uint32_t qfh[4][4], qfl[4][4];
#pragma unroll
    for (int ka = 0; ka < 4; ka++) {
        int off = a_row * QPITCH + ka * 16 + a_col;
        ldsm4(qfh[ka], smem_u32(&Qs_hi[off]));
        ldsm4(qfl[ka], smem_u32(&Qs_lo[off]));
    }

    const int k_row = (lane & 7) + 8 * (lane >> 4);
    const int k_col = 8 * ((lane >> 3) & 1);
    const int v_row = (lane & 7) + 8 * ((lane >> 3) & 1);
    const int v_col = 8 * (lane >> 4);

    float m0 = -1e30f, m1 = -1e30f, l0 = 0.f, l1 = 0.f;
    float o[8][4];
#pragma unroll
    for (int j = 0; j < 8; j++)
#pragma unroll
        for (int e = 0; e < 4; e++) o[j][e] = 0.f;

    for (int kt = 0; kt < SEQ / 64; kt++) {
        const __nv_bfloat16* sb = smb + 2 * Q_PL + (kt & 1) * KV_STG;
        const __nv_bfloat16* Ksh = sb;
        const __nv_bfloat16* Ksl = sb + Q_PL;
        const __nv_bfloat16* Vsh = sb + 2 * Q_PL;
        const __nv_bfloat16* Vsl = sb + 3 * Q_PL;

        // ---- S = Q K^T: 16 steps with K-fragment double buffering ----
        float s[8][4];
#pragma unroll
        for (int j = 0; j < 8; j++)
#pragma unroll
            for (int e = 0; e < 4; e++) s[j][e] = 0.f;

        uint32_t kfh[2][4], kfl[2][4];
        {
            int off0 = k_row * QPITCH + k_col;   // nb=0, ka=0
            ldsm4(kfh[0], smem_u32(Ksh + off0));
            ldsm4(kfl[0], smem_u32(Ksl + off0));
        }
#pragma unroll
        for (int step = 0; step < 16; step++) {
            const int nb = step >> 2, ka = step & 3;
            const int cur = step & 1, nxt = cur ^ 1;
            if (step < 15) {
                const int s2 = step + 1;
                const int nb2 = s2 >> 2, ka2 = s2 & 3;
                int off = (nb2 * 16 + k_row) * QPITCH + ka2 * 16 + k_col;
                ldsm4(kfh[nxt], smem_u32(Ksh + off));
                ldsm4(kfl[nxt], smem_u32(Ksl + off));
            }
            mma16816(s[2*nb],   qfh[ka], &kfh[cur][0]);
            mma16816(s[2*nb+1], qfh[ka], &kfh[cur][2]);
            mma16816(s[2*nb],   qfh[ka], &kfl[cur][0]);
            mma16816(s[2*nb+1], qfh[ka], &kfl[cur][2]);
            mma16816(s[2*nb],   qfl[ka], &kfh[cur][0]);
            mma16816(s[2*nb+1], qfl[ka], &kfh[cur][2]);
        }

        // ---- online softmax ----
        float mx0 = -1e30f, mx1 = -1e30f;
#pragma unroll
        for (int j = 0; j < 8; j++) {
            s[j][0] *= scale; s[j][1] *= scale; s[j][2] *= scale; s[j][3] *= scale;
            mx0 = fmaxf(mx0, fmaxf(s[j][0], s[j][1]));
            mx1 = fmaxf(mx1, fmaxf(s[j][2], s[j][3]));
        }
        mx0 = fmaxf(mx0, __shfl_xor_sync(0xffffffffu, mx0, 1));
        mx0 = fmaxf(mx0, __shfl_xor_sync(0xffffffffu, mx0, 2));
        mx1 = fmaxf(mx1, __shfl_xor_sync(0xffffffffu, mx1, 1));
        mx1 = fmaxf(mx1, __shfl_xor_sync(0xffffffffu, mx1, 2));
        float mn0 = fmaxf(m0, mx0), mn1 = fmaxf(m1, mx1);
        float c0 = __expf(m0 - mn0), c1 = __expf(m1 - mn1);
        float p[8][4];
        float ls0 = 0.f, ls1 = 0.f;
#pragma unroll
        for (int j = 0; j < 8; j++) {
            p[j][0] = __expf(s[j][0] - mn0); p[j][1] = __expf(s[j][1] - mn0);
            p[j][2] = __expf(s[j][2] - mn1); p[j][3] = __expf(s[j][3] - mn1);
            ls0 += p[j][0] + p[j][1];
            ls1 += p[j][2] + p[j][3];
        }
        ls0 += __shfl_xor_sync(0xffffffffu, ls0, 1);
        ls0 += __shfl_xor_sync(0xffffffffu, ls0, 2);
        ls1 += __shfl_xor_sync(0xffffffffu, ls1, 1);
        ls1 += __shfl_xor_sync(0xffffffffu, ls1, 2);
        l0 = l0 * c0 + ls0; m0 = mn0;
        l1 = l1 * c1 + ls1; m1 = mn1;
#pragma unroll
        for (int j = 0; j < 8; j++) {
            o[j][0] *= c0; o[j][1] *= c0; o[j][2] *= c1; o[j][3] *= c1;
        }

        // ---- P fragments ----
        uint32_t pfh[4][4], pfl[4][4];
#pragma unroll
        for (int ka = 0; ka < 4; ka++) {
            split2(p[2*ka][0],   p[2*ka][1],   pfh[ka][0], pfl[ka][0]);
            split2(p[2*ka][2],   p[2*ka][3],   pfh[ka][1], pfl[ka][1]);
            split2(p[2*ka+1][0], p[2*ka+1][1], pfh[ka][2], pfl[ka][2]);
            split2(p[2*ka+1][2], p[2*ka+1][3], pfh[ka][3], pfl[ka][3]);
        }

        // ---- O += P V: 16 steps with V-fragment double buffering ----
        uint32_t vfh[2][4], vfl[2][4];
        {
            int off0 = v_row * QPITCH + v_col;   // nb=0, ka=0
            ldsm4t(vfh[0], smem_u32(Vsh + off0));
            ldsm4t(vfl[0], smem_u32(Vsl + off0));
        }
#pragma unroll
        for (int step = 0; step < 16; step++) {
            const int nb = step >> 2, ka = step & 3;
            const int cur = step & 1, nxt = cur ^ 1;
            if (step < 15) {
                const int s2 = step + 1;
                const int nb2 = s2 >> 2, ka2 = s2 & 3;
                int off = (ka2 * 16 + v_row) * QPITCH + nb2 * 16 + v_col;
                ldsm4t(vfh[nxt], smem_u32(Vsh + off));
                ldsm4t(vfl[nxt], smem_u32(Vsl + off));
            }
            mma16816(o[2*nb],   pfh[ka], &vfh[cur][0]);
            mma16816(o[2*nb+1], pfh[ka], &vfh[cur][2]);
            mma16816(o[2*nb],   pfh[ka], &vfl[cur][0]);
            mma16816(o[2*nb+1], pfh[ka], &vfl[cur][2]);
            mma16816(o[2*nb],   pfl[ka], &vfh[cur][0]);
            mma16816(o[2*nb+1], pfl[ka], &vfh[cur][2]);
        }

        __syncthreads();
        issue_kv(kt + 2);
        CP_WAIT1();
        __syncthreads();
    }

    float i0 = 1.f / l0, i1 = 1.f / l1;
    int b = bh / HEADS, h = bh - (bh / HEADS) * HEADS;
    int srow0 = qt * 64 + warp * 16 + g;
    int srow1 = srow0 + 8;
#pragma unroll
    for (int j = 0; j < 8; j++) {
        int col = h * HDIM + j * 8 + 2 * t;
        size_t i0x = ((size_t)(b * SEQ) + srow0) * DIM + col;
        size_t i1x = ((size_t)(b * SEQ) + srow1) * DIM + col;
        uint32_t hi, lo;
        split2(o[j][0] * i0, o[j][1] * i0, hi, lo);
        *(uint32_t*)(g_o_hi + i0x) = hi;
        *(uint32_t*)(g_o_lo + i0x) = lo;
        split2(o[j][2] * i1, o[j][3] * i1, hi, lo);
        *(uint32_t*)(g_o_hi + i1x) = hi;
        *(uint32_t*)(g_o_lo + i1x) = lo;
    }
}

// ===========================================================================
extern "C" void kernel_launch(void* const* d_in, const int* in_sizes, int n_in,
                              void* d_out, int out_size) {
    const float* x      = (const float*)d_in[0];
    const float* w_qkv  = (const float*)d_in[1];
    const float* b_qkv  = (const float*)d_in[2];
    const float* w_proj = (const float*)d_in[3];
    const float* b_proj = (const float*)d_in[4];
    float* out = (float*)d_out;

    cudaFuncSetAttribute(attn_kernel, cudaFuncAttributeMaxDynamicSharedMemorySize,
                         AT_SMEM_BYTES);
    cudaFuncSetAttribute(mma_gemm_kernel<true>, cudaFuncAttributeMaxDynamicSharedMemorySize,
                         GEMM_SMEM_B);
    cudaFuncSetAttribute(mma_gemm_kernel<false>, cudaFuncAttributeMaxDynamicSharedMemorySize,
                         GEMM_SMEM_B);

    // prep
    split_x_kernel<<<M_ROWS * DIM / 1024, 256>>>(x);
    tsplit_kernel<0><<<dim3(N_QKV / 32, DIM / 32), 256>>>(w_qkv, DIM, N_QKV);
    tsplit_kernel<1><<<dim3(DIM / 32, DIM / 32), 256>>>(w_proj, DIM, DIM);

    // QKV GEMM: M=8192, N=2304
    mma_gemm_kernel<true><<<dim3(N_QKV / 256, M_ROWS / 64), 128, GEMM_SMEM_B>>>(
        b_qkv, nullptr);

    // attention
    attn_kernel<<<dim3(SEQ / 64, BATCH * HEADS), 128, AT_SMEM_BYTES>>>();

    // proj GEMM: M=8192, N=768
    mma_gemm_kernel<false><<<dim3(DIM / 256, M_ROWS / 64), 128, GEMM_SMEM_B>>>(
        b_proj, out);
}

// round 14
// speedup vs baseline: 1.1747x; 1.1082x over previous
#include <cuda_runtime.h>
#include <cuda_bf16.h>
#include <cuda_fp16.h>
#include <math.h>
#include <stdint.h>

#define BATCH 8
#define SEQ   1024
#define DIM   768
#define HEADS 12
#define HDIM  64
#define M_ROWS (BATCH*SEQ)        // 8192
#define N_QKV  (3*DIM)            // 2304
#define NKT    (DIM/32)           // 24 k-tiles of 32

#define DINLINE __device__ __forceinline__

// ---------------- scratch planes (device-code references ONLY) ----------------
#define QKV_ELEMS (BATCH*HEADS*SEQ*HDIM)
__device__ __half g_q_hi[QKV_ELEMS], g_q_lo[QKV_ELEMS];     // Q: fp16 pair
__device__ __half g_k_hi[QKV_ELEMS];                        // K: fp16 single
__device__ __half g_v_hi[QKV_ELEMS];                        // V: fp16 single
__device__ __nv_bfloat16 g_o_hi[M_ROWS*DIM], g_o_lo[M_ROWS*DIM];   // O: bf16 pair (proj A)
__device__ __nv_bfloat16 g_x_hi[M_ROWS*DIM], g_x_lo[M_ROWS*DIM];   // x split, K-major
__device__ __nv_bfloat16 g_wq_hi[N_QKV*DIM], g_wq_lo[N_QKV*DIM];   // w_qkv^T [N][K]
__device__ __nv_bfloat16 g_wp_hi[DIM*DIM],  g_wp_lo[DIM*DIM];      // w_proj^T [N][K]

// ---------------- PTX helpers ----------------
DINLINE uint32_t smem_u32(const void* p) { return (uint32_t)__cvta_generic_to_shared(p); }

DINLINE void ldsm4(uint32_t r[4], uint32_t a) {
    asm volatile("ldmatrix.sync.aligned.m8n8.x4.shared.b16 {%0,%1,%2,%3},[%4];"
                 : "=r"(r[0]), "=r"(r[1]), "=r"(r[2]), "=r"(r[3]) : "r"(a));
}
DINLINE void ldsm4t(uint32_t r[4], uint32_t a) {
    asm volatile("ldmatrix.sync.aligned.m8n8.x4.trans.shared.b16 {%0,%1,%2,%3},[%4];"
                 : "=r"(r[0]), "=r"(r[1]), "=r"(r[2]), "=r"(r[3]) : "r"(a));
}
// bf16 MMA (GEMMs)
DINLINE void mma16816(float c[4], const uint32_t a[4], const uint32_t b[2]) {
    asm volatile("mma.sync.aligned.m16n8k16.row.col.f32.bf16.bf16.f32 "
                 "{%0,%1,%2,%3},{%4,%5,%6,%7},{%8,%9},{%0,%1,%2,%3};"
                 : "+f"(c[0]), "+f"(c[1]), "+f"(c[2]), "+f"(c[3])
                 : "r"(a[0]), "r"(a[1]), "r"(a[2]), "r"(a[3]), "r"(b[0]), "r"(b[1]));
}
// fp16 MMA (attention)
DINLINE void mma16816h(float c[4], const uint32_t a[4], const uint32_t b[2]) {
    asm volatile("mma.sync.aligned.m16n8k16.row.col.f32.f16.f16.f32 "
                 "{%0,%1,%2,%3},{%4,%5,%6,%7},{%8,%9},{%0,%1,%2,%3};"
                 : "+f"(c[0]), "+f"(c[1]), "+f"(c[2]), "+f"(c[3])
                 : "r"(a[0]), "r"(a[1]), "r"(a[2]), "r"(a[3]), "r"(b[0]), "r"(b[1]));
}
DINLINE void cp16(uint32_t dst, const void* src) {
    asm volatile("cp.async.cg.shared.global [%0], [%1], 16;" :: "r"(dst), "l"(src) : "memory");
}
#define CP_COMMIT() asm volatile("cp.async.commit_group;" ::: "memory")
#define CP_WAIT1()  asm volatile("cp.async.wait_group 1;" ::: "memory")

// split fp32 pair into packed bf16 hi/lo
DINLINE void split2(float x, float y, uint32_t &hi, uint32_t &lo) {
    __nv_bfloat16 hx = __float2bfloat16(x);
    __nv_bfloat16 hy = __float2bfloat16(y);
    float rx = x - __bfloat162float(hx);
    float ry = y - __bfloat162float(hy);
    __nv_bfloat162 h2; h2.x = hx; h2.y = hy;
    __nv_bfloat162 l2; l2.x = __float2bfloat16(rx); l2.y = __float2bfloat16(ry);
    hi = *reinterpret_cast<uint32_t*>(&h2);
    lo = *reinterpret_cast<uint32_t*>(&l2);
}
// split fp32 pair into packed fp16 hi/lo
DINLINE void split2h(float x, float y, uint32_t &hi, uint32_t &lo) {
    __half hx = __float2half_rn(x);
    __half hy = __float2half_rn(y);
    float rx = x - __half2float(hx);
    float ry = y - __half2float(hy);
    __half2 h2 = __halves2half2(hx, hy);
    __half2 l2 = __halves2half2(__float2half_rn(rx), __float2half_rn(ry));
    hi = *reinterpret_cast<uint32_t*>(&h2);
    lo = *reinterpret_cast<uint32_t*>(&l2);
}
DINLINE uint32_t pack2h(float x, float y) {
    __half2 h2 = __halves2half2(__float2half_rn(x), __float2half_rn(y));
    return *reinterpret_cast<uint32_t*>(&h2);
}

// ===========================================================================
// Prep kernels
// ===========================================================================
__global__ __launch_bounds__(256) void split_x_kernel(const float* __restrict__ x) {
    int i = blockIdx.x * 256 + threadIdx.x;   // one float4
    float4 v = ((const float4*)x)[i];
    uint32_t h0, l0, h1, l1;
    split2(v.x, v.y, h0, l0);
    split2(v.z, v.w, h1, l1);
    ((uint2*)g_x_hi)[i] = make_uint2(h0, h1);
    ((uint2*)g_x_lo)[i] = make_uint2(l0, l1);
}

// src [K][N] fp32 -> plane set WSEL (0: w_qkv->g_wq, 1: w_proj->g_wp), [N][K] bf16 hi/lo
template <int WSEL>
__global__ __launch_bounds__(256) void tsplit_kernel(
    const float* __restrict__ src, int K, int N)
{
    __nv_bfloat16* dh = (WSEL == 0) ? g_wq_hi : g_wp_hi;
    __nv_bfloat16* dl = (WSEL == 0) ? g_wq_lo : g_wp_lo;
    __shared__ float T[32][33];
    int k0 = blockIdx.y * 32, n0 = blockIdx.x * 32;
    int tx = threadIdx.x & 31, ty = threadIdx.x >> 5;
#pragma unroll
    for (int i = 0; i < 4; i++)
        T[ty + 8 * i][tx] = src[(size_t)(k0 + ty + 8 * i) * N + n0 + tx];
    __syncthreads();
#pragma unroll
    for (int i = 0; i < 4; i++) {
        float v = T[tx][ty + 8 * i];
        __nv_bfloat16 h = __float2bfloat16(v);
        size_t o = (size_t)(n0 + ty + 8 * i) * K + k0 + tx;
        dh[o] = h;
        dl[o] = __float2bfloat16(v - __bfloat162float(h));
    }
}

// ===========================================================================
// bf16x3 mma.sync GEMM (R12 — best measured). Block 64x256, 4 warps,
// warp tile 64x64, BK=32, 2-stage cp.async, B-fragment prefetch.
// ===========================================================================
#define PAe 40                       // smem pitch in bf16 elems (80B): conflict-free
#define A_STG (64*PAe)               // elems per A plane per stage
#define B_STG (256*PAe)
#define STG_ELEMS (2*A_STG + 2*B_STG)          // 25600 elems
#define GEMM_SMEM_B (2 * STG_ELEMS * 2)        // 102400 bytes

template <bool QKV_EPI>
__global__ __launch_bounds__(128, 2) void mma_gemm_kernel(
    const float* __restrict__ bias, float* __restrict__ out)
{
    const __nv_bfloat16* Ah = QKV_EPI ? g_x_hi : g_o_hi;
    const __nv_bfloat16* Al = QKV_EPI ? g_x_lo : g_o_lo;
    const __nv_bfloat16* Bh = QKV_EPI ? g_wq_hi : g_wp_hi;
    const __nv_bfloat16* Bl = QKV_EPI ? g_wq_lo : g_wp_lo;

    extern __shared__ __nv_bfloat16 sm[];
    const int tid = threadIdx.x, lane = tid & 31, warp = tid >> 5;
    const int rowBase = blockIdx.y * 64, colBase = blockIdx.x * 256;

    float acc[4][8][4];
#pragma unroll
    for (int i = 0; i < 4; i++)
#pragma unroll
        for (int j = 0; j < 8; j++)
#pragma unroll
            for (int e = 0; e < 4; e++) acc[i][j][e] = 0.f;

    auto issue = [&](int st) {
        if (st < NKT) {
            const int k0 = st * 32;
            __nv_bfloat16* base = sm + (st & 1) * STG_ELEMS;
#pragma unroll
            for (int i = 0; i < 2; i++) {
                int id = tid + i * 128;
                int r = id >> 2, c8 = (id & 3) * 8;
                uint32_t d = smem_u32(base + r * PAe + c8);
                size_t s = (size_t)(rowBase + r) * DIM + k0 + c8;
                cp16(d, Ah + s);
                cp16(d + A_STG * 2, Al + s);
            }
#pragma unroll
            for (int i = 0; i < 8; i++) {
                int id = tid + i * 128;
                int r = id >> 2, c8 = (id & 3) * 8;
                uint32_t d = smem_u32(base + 2 * A_STG + r * PAe + c8);
                size_t s = (size_t)(colBase + r) * DIM + k0 + c8;
                cp16(d, Bh + s);
                cp16(d + B_STG * 2, Bl + s);
            }
        }
        CP_COMMIT();
    };

    issue(0);
    issue(1);

    const int a_ro = (lane & 7) + 8 * ((lane >> 3) & 1);
    const int a_co = 8 * (lane >> 4);
    const int b_ro = (lane & 7) + 8 * (lane >> 4);
    const int b_co = 8 * ((lane >> 3) & 1);

    for (int t = 0; t < NKT; t++) {
        CP_WAIT1();
        __syncthreads();
        const __nv_bfloat16* stg = sm + (t & 1) * STG_ELEMS;
        const __nv_bfloat16* sAh = stg;
        const __nv_bfloat16* sAl = stg + A_STG;
        const __nv_bfloat16* sBh = stg + 2 * A_STG;
        const __nv_bfloat16* sBl = stg + 2 * A_STG + B_STG;

        uint32_t afh[2][4][4], afl[2][4][4];
#pragma unroll
        for (int ks = 0; ks < 2; ks++)
#pragma unroll
            for (int ma = 0; ma < 4; ma++) {
                int off = (ma * 16 + a_ro) * PAe + ks * 16 + a_co;
                ldsm4(afh[ks][ma], smem_u32(sAh + off));
                ldsm4(afl[ks][ma], smem_u32(sAl + off));
            }

        uint32_t bfh[2][4], bfl[2][4];
        {
            int off0 = (warp * 64 + b_ro) * PAe + b_co;
            ldsm4(bfh[0], smem_u32(sBh + off0));
            ldsm4(bfl[0], smem_u32(sBl + off0));
        }
#pragma unroll
        for (int step = 0; step < 8; step++) {
            const int ks = step >> 2, nb = step & 3;
            const int cur = step & 1, nxt = cur ^ 1;
            if (step < 7) {
                const int s2 = step + 1;
                const int ks2 = s2 >> 2, nb2 = s2 & 3;
                int off = (warp * 64 + nb2 * 16 + b_ro) * PAe + ks2 * 16 + b_co;
                ldsm4(bfh[nxt], smem_u32(sBh + off));
                ldsm4(bfl[nxt], smem_u32(sBl + off));
            }
#pragma unroll
            for (int ma = 0; ma < 4; ma++) {
                mma16816(acc[ma][2*nb],   afh[ks][ma], &bfh[cur][0]);
                mma16816(acc[ma][2*nb+1], afh[ks][ma], &bfh[cur][2]);
                mma16816(acc[ma][2*nb],   afh[ks][ma], &bfl[cur][0]);
                mma16816(acc[ma][2*nb+1], afh[ks][ma], &bfl[cur][2]);
                mma16816(acc[ma][2*nb],   afl[ks][ma], &bfh[cur][0]);
                mma16816(acc[ma][2*nb+1], afl[ks][ma], &bfh[cur][2]);
            }
        }
        __syncthreads();
        issue(t + 2);
    }

    // ---------------- epilogue ----------------
    const int g = lane >> 2, tq = lane & 3;
#pragma unroll
    for (int ma = 0; ma < 4; ma++) {
#pragma unroll
        for (int half = 0; half < 2; half++) {
            int row = rowBase + ma * 16 + g + half * 8;
            if (QKV_EPI) {
                int b = row >> 10, srow = row & 1023;
#pragma unroll
                for (int nn = 0; nn < 8; nn++) {
                    int col = colBase + warp * 64 + nn * 8 + 2 * tq;
                    float v0 = acc[ma][nn][half * 2 + 0] + bias[col];
                    float v1 = acc[ma][nn][half * 2 + 1] + bias[col + 1];
                    int which = col / DIM;
                    int rem = col - which * DIM;
                    int h = rem >> 6, d = rem & 63;
                    size_t idx = (((size_t)(b * HEADS + h)) * SEQ + srow) * HDIM + d;
                    if (which == 0) {          // Q: fp16 pair
                        uint32_t hi, lo;
                        split2h(v0, v1, hi, lo);
                        *(uint32_t*)(g_q_hi + idx) = hi;
                        *(uint32_t*)(g_q_lo + idx) = lo;
                    } else if (which == 1) {   // K: fp16 single
                        *(uint32_t*)(g_k_hi + idx) = pack2h(v0, v1);
                    } else {                   // V: fp16 single
                        *(uint32_t*)(g_v_hi + idx) = pack2h(v0, v1);
                    }
                }
            } else {
#pragma unroll
                for (int nn = 0; nn < 8; nn++) {
                    int col = colBase + warp * 64 + nn * 8 + 2 * tq;
                    float2 o;
                    o.x = acc[ma][nn][half * 2 + 0] + bias[col];
                    o.y = acc[ma][nn][half * 2 + 1] + bias[col + 1];
                    *(float2*)(out + (size_t)row * DIM + col) = o;
                }
            }
        }
    }
}

// ===========================================================================
// Flash attention: fp16 2-term. Br=64, 4 warps, 2 CTAs/SM, cp.async 2-stage.
// Q/P fp16 pairs; K/V fp16 single plane. 4 MMAs per step (was 6).
// ===========================================================================
#define QPITCH 72
#define Q_PL (64*QPITCH)                  // 4608 elems per plane
#define KV_STG (2*Q_PL)                   // K + V single planes per stage
#define AT_SMEM_BYTES ((2*Q_PL + 2*KV_STG) * 2)   // 55296 bytes

__global__ __launch_bounds__(128, 2) void attn_kernel()
{
    extern __shared__ __half smb[];
    const int tid = threadIdx.x, lane = tid & 31, warp = tid >> 5;
    const int bh = blockIdx.y, qt = blockIdx.x;
    const int g = lane >> 2, t = lane & 3;
    const float scale = 0.125f;

    const size_t base = (size_t)bh * SEQ * HDIM;
    const __half* qh = g_q_hi + base; const __half* ql = g_q_lo + base;
    const __half* kh = g_k_hi + base;
    const __half* vh = g_v_hi + base;

    __half* Qs_hi = smb;
    __half* Qs_lo = smb + Q_PL;

#pragma unroll
    for (int i = 0; i < 4; i++) {
        int id = tid + i * 128;
        int r = id >> 3, c8 = (id & 7) * 8;
        size_t s = (size_t)(qt * 64 + r) * HDIM + c8;
        cp16(smem_u32(Qs_hi + r * QPITCH + c8), qh + s);
        cp16(smem_u32(Qs_lo + r * QPITCH + c8), ql + s);
    }

    auto issue_kv = [&](int kt) {
        if (kt < SEQ / 64) {
            __half* sb = smb + 2 * Q_PL + (kt & 1) * KV_STG;
#pragma unroll
            for (int i = 0; i < 4; i++) {
                int id = tid + i * 128;
                int r = id >> 3, c8 = (id & 7) * 8;
                int doff = r * QPITCH + c8;
                size_t s = (size_t)(kt * 64 + r) * HDIM + c8;
                cp16(smem_u32(sb + doff),        kh + s);
                cp16(smem_u32(sb + Q_PL + doff), vh + s);
            }
        }
        CP_COMMIT();
    };

    issue_kv(0);
    issue_kv(1);

    CP_WAIT1();
    __syncthreads();

    const int a_row = warp * 16 + (lane & 7) + 8 * ((lane >> 3) & 1);
    const int a_col = 8 * (lane >> 4);
    uint32_t qfh[4][4], qfl[4][4];
#pragma unroll
    for (int ka = 0; ka < 4; ka++) {
        int off = a_row * QPITCH + ka * 16 + a_col;
        ldsm4(qfh[ka], smem_u32(&Qs_hi[off]));
        ldsm4(qfl[ka], smem_u32(&Qs_lo[off]));
    }

    const int k_row = (lane & 7) + 8 * (lane >> 4);
    const int k_col = 8 * ((lane >> 3) & 1);
    const int v_row = (lane & 7) + 8 * ((lane >> 3) & 1);
    const int v_col = 8 * (lane >> 4);

    float m0 = -1e30f, m1 = -1e30f, l0 = 0.f, l1 = 0.f;
    float o[8][4];
#pragma unroll
    for (int j = 0; j < 8; j++)
#pragma unroll
        for (int e = 0; e < 4; e++) o[j][e] = 0.f;

    for (int kt = 0; kt < SEQ / 64; kt++) {
        const __half* sb = smb + 2 * Q_PL + (kt & 1) * KV_STG;
        const __half* Ksh = sb;
        const __half* Vsh = sb + Q_PL;

        // ---- S = (Qh+Ql) Kh^T : 16 steps, K-fragment double buffered ----
        float s[8][4];
#pragma unroll
        for (int j = 0; j < 8; j++)
#pragma unroll
            for (int e = 0; e < 4; e++) s[j][e] = 0.f;

        uint32_t kfh[2][4];
        {
            int off0 = k_row * QPITCH + k_col;
            ldsm4(kfh[0], smem_u32(Ksh + off0));
        }
#pragma unroll
        for (int step = 0; step < 16; step++) {
            const int nb = step >> 2, ka = step & 3;
            const int cur = step & 1, nxt = cur ^ 1;
            if (step < 15) {
                const int s2 = step + 1;
                const int nb2 = s2 >> 2, ka2 = s2 & 3;
                int off = (nb2 * 16 + k_row) * QPITCH + ka2 * 16 + k_col;
                ldsm4(kfh[nxt], smem_u32(Ksh + off));
            }
            mma16816h(s[2*nb],   qfh[ka], &kfh[cur][0]);
            mma16816h(s[2*nb+1], qfh[ka], &kfh[cur][2]);
            mma16816h(s[2*nb],   qfl[ka], &kfh[cur][0]);
            mma16816h(s[2*nb+1], qfl[ka], &kfh[cur][2]);
        }

        // ---- online softmax ----
        float mx0 = -1e30f, mx1 = -1e30f;
#pragma unroll
        for (int j = 0; j < 8; j++) {
            s[j][0] *= scale; s[j][1] *= scale; s[j][2] *= scale; s[j][3] *= scale;
            mx0 = fmaxf(mx0, fmaxf(s[j][0], s[j][1]));
            mx1 = fmaxf(mx1, fmaxf(s[j][2], s[j][3]));
        }
        mx0 = fmaxf(mx0, __shfl_xor_sync(0xffffffffu, mx0, 1));
        mx0 = fmaxf(mx0, __shfl_xor_sync(0xffffffffu, mx0, 2));
        mx1 = fmaxf(mx1, __shfl_xor_sync(0xffffffffu, mx1, 1));
        mx1 = fmaxf(mx1, __shfl_xor_sync(0xffffffffu, mx1, 2));
        float mn0 = fmaxf(m0, mx0), mn1 = fmaxf(m1, mx1);
        float c0 = __expf(m0 - mn0), c1 = __expf(m1 - mn1);
        float p[8][4];
        float ls0 = 0.f, ls1 = 0.f;
#pragma unroll
        for (int j = 0; j < 8; j++) {
            p[j][0] = __expf(s[j][0] - mn0); p[j][1] = __expf(s[j][1] - mn0);
            p[j][2] = __expf(s[j][2] - mn1); p[j][3] = __expf(s[j][3] - mn1);
            ls0 += p[j][0] + p[j][1];
            ls1 += p[j][2] + p[j][3];
        }
        ls0 += __shfl_xor_sync(0xffffffffu, ls0, 1);
        ls0 += __shfl_xor_sync(0xffffffffu, ls0, 2);
        ls1 += __shfl_xor_sync(0xffffffffu, ls1, 1);
        ls1 += __shfl_xor_sync(0xffffffffu, ls1, 2);
        l0 = l0 * c0 + ls0; m0 = mn0;
        l1 = l1 * c1 + ls1; m1 = mn1;
#pragma unroll
        for (int j = 0; j < 8; j++) {
            o[j][0] *= c0; o[j][1] *= c0; o[j][2] *= c1; o[j][3] *= c1;
        }

        // ---- P fragments (fp16 pair) ----
        uint32_t pfh[4][4], pfl[4][4];
#pragma unroll
        for (int ka = 0; ka < 4; ka++) {
            split2h(p[2*ka][0],   p[2*ka][1],   pfh[ka][0], pfl[ka][0]);
            split2h(p[2*ka][2],   p[2*ka][3],   pfh[ka][1], pfl[ka][1]);
            split2h(p[2*ka+1][0], p[2*ka+1][1], pfh[ka][2], pfl[ka][2]);
            split2h(p[2*ka+1][2], p[2*ka+1][3], pfh[ka][3], pfl[ka][3]);
        }

        // ---- O += (Ph+Pl) Vh : 16 steps, V-fragment double buffered ----
        uint32_t vfh[2][4];
        {
            int off0 = v_row * QPITCH + v_col;
            ldsm4t(vfh[0], smem_u32(Vsh + off0));
        }
#pragma unroll
        for (int step = 0; step < 16; step++) {
            const int nb = step >> 2, ka = step & 3;
            const int cur = step & 1, nxt = cur ^ 1;
            if (step < 15) {
                const int s2 = step + 1;
                const int nb2 = s2 >> 2, ka2 = s2 & 3;
                int off = (ka2 * 16 + v_row) * QPITCH + nb2 * 16 + v_col;
                ldsm4t(vfh[nxt], smem_u32(Vsh + off));
            }
            mma16816h(o[2*nb],   pfh[ka], &vfh[cur][0]);
            mma16816h(o[2*nb+1], pfh[ka], &vfh[cur][2]);
            mma16816h(o[2*nb],   pfl[ka], &vfh[cur][0]);
            mma16816h(o[2*nb+1], pfl[ka], &vfh[cur][2]);
        }

        __syncthreads();
        issue_kv(kt + 2);
        CP_WAIT1();
        __syncthreads();
    }

    // ---- normalize + write O as bf16 pair into [B,S,D] planes ----
    float i0 = 1.f / l0, i1 = 1.f / l1;
    int b = bh / HEADS, h = bh - (bh / HEADS) * HEADS;
    int srow0 = qt * 64 + warp * 16 + g;
    int srow1 = srow0 + 8;
#pragma unroll
    for (int j = 0; j < 8; j++) {
        int col = h * HDIM + j * 8 + 2 * t;
        size_t i0x = ((size_t)(b * SEQ) + srow0) * DIM + col;
        size_t i1x = ((size_t)(b * SEQ) + srow1) * DIM + col;
        uint32_t hi, lo;
        split2(o[j][0] * i0, o[j][1] * i0, hi, lo);
        *(uint32_t*)(g_o_hi + i0x) = hi;
        *(uint32_t*)(g_o_lo + i0x) = lo;
        split2(o[j][2] * i1, o[j][3] * i1, hi, lo);
        *(uint32_t*)(g_o_hi + i1x) = hi;
        *(uint32_t*)(g_o_lo + i1x) = lo;
    }
}

// ===========================================================================
extern "C" void kernel_launch(void* const* d_in, const int* in_sizes, int n_in,
                              void* d_out, int out_size) {
    const float* x      = (const float*)d_in[0];
    const float* w_qkv  = (const float*)d_in[1];
    const float* b_qkv  = (const float*)d_in[2];
    const float* w_proj = (const float*)d_in[3];
    const float* b_proj = (const float*)d_in[4];
    float* out = (float*)d_out;

    cudaFuncSetAttribute(attn_kernel, cudaFuncAttributeMaxDynamicSharedMemorySize,
                         AT_SMEM_BYTES);
    cudaFuncSetAttribute(mma_gemm_kernel<true>, cudaFuncAttributeMaxDynamicSharedMemorySize,
                         GEMM_SMEM_B);
    cudaFuncSetAttribute(mma_gemm_kernel<false>, cudaFuncAttributeMaxDynamicSharedMemorySize,
                         GEMM_SMEM_B);

    // prep
    split_x_kernel<<<M_ROWS * DIM / 1024, 256>>>(x);
    tsplit_kernel<0><<<dim3(N_QKV / 32, DIM / 32), 256>>>(w_qkv, DIM, N_QKV);
    tsplit_kernel<1><<<dim3(DIM / 32, DIM / 32), 256>>>(w_proj, DIM, DIM);

    // QKV GEMM: M=8192, N=2304
    mma_gemm_kernel<true><<<dim3(N_QKV / 256, M_ROWS / 64), 128, GEMM_SMEM_B>>>(
        b_qkv, nullptr);

    // attention
    attn_kernel<<<dim3(SEQ / 64, BATCH * HEADS), 128, AT_SMEM_BYTES>>>();

    // proj GEMM: M=8192, N=768
    mma_gemm_kernel<false><<<dim3(DIM / 256, M_ROWS / 64), 128, GEMM_SMEM_B>>>(
        b_proj, out);
}

// round 15
// speedup vs baseline: 1.5253x; 1.2984x over previous
#include <cuda_runtime.h>
#include <cuda_fp16.h>
#include <math.h>
#include <stdint.h>

#define BATCH 8
#define SEQ   1024
#define DIM   768
#define HEADS 12
#define HDIM  64
#define M_ROWS (BATCH*SEQ)        // 8192
#define N_QKV  (3*DIM)            // 2304
#define NKT    (DIM/32)           // 24 k-tiles of 32

#define DINLINE __device__ __forceinline__

// ---------------- scratch planes (device-code references ONLY) ----------------
// fp16 2-term everywhere: A-side operands (x, Q, P, O) as (hi,lo) pairs;
// B-side operands (weights, K, V) single fp16.
#define QKV_ELEMS (BATCH*HEADS*SEQ*HDIM)
__device__ __half g_q_hi[QKV_ELEMS], g_q_lo[QKV_ELEMS];
__device__ __half g_k_hi[QKV_ELEMS];
__device__ __half g_v_hi[QKV_ELEMS];
__device__ __half g_o_hi[M_ROWS*DIM], g_o_lo[M_ROWS*DIM];
__device__ __half g_x_hi[M_ROWS*DIM], g_x_lo[M_ROWS*DIM];
__device__ __half g_wq_hi[N_QKV*DIM];                     // w_qkv^T [N][K]
__device__ __half g_wp_hi[DIM*DIM];                       // w_proj^T [N][K]

// ---------------- PTX helpers ----------------
DINLINE uint32_t smem_u32(const void* p) { return (uint32_t)__cvta_generic_to_shared(p); }

DINLINE void ldsm4(uint32_t r[4], uint32_t a) {
    asm volatile("ldmatrix.sync.aligned.m8n8.x4.shared.b16 {%0,%1,%2,%3},[%4];"
                 : "=r"(r[0]), "=r"(r[1]), "=r"(r[2]), "=r"(r[3]) : "r"(a));
}
DINLINE void ldsm4t(uint32_t r[4], uint32_t a) {
    asm volatile("ldmatrix.sync.aligned.m8n8.x4.trans.shared.b16 {%0,%1,%2,%3},[%4];"
                 : "=r"(r[0]), "=r"(r[1]), "=r"(r[2]), "=r"(r[3]) : "r"(a));
}
DINLINE void mma16816h(float c[4], const uint32_t a[4], const uint32_t b[2]) {
    asm volatile("mma.sync.aligned.m16n8k16.row.col.f32.f16.f16.f32 "
                 "{%0,%1,%2,%3},{%4,%5,%6,%7},{%8,%9},{%0,%1,%2,%3};"
                 : "+f"(c[0]), "+f"(c[1]), "+f"(c[2]), "+f"(c[3])
                 : "r"(a[0]), "r"(a[1]), "r"(a[2]), "r"(a[3]), "r"(b[0]), "r"(b[1]));
}
DINLINE void cp16(uint32_t dst, const void* src) {
    asm volatile("cp.async.cg.shared.global [%0], [%1], 16;" :: "r"(dst), "l"(src) : "memory");
}
#define CP_COMMIT() asm volatile("cp.async.commit_group;" ::: "memory")
#define CP_WAIT1()  asm volatile("cp.async.wait_group 1;" ::: "memory")

// split fp32 pair into packed fp16 hi/lo
DINLINE void split2h(float x, float y, uint32_t &hi, uint32_t &lo) {
    __half hx = __float2half_rn(x);
    __half hy = __float2half_rn(y);
    float rx = x - __half2float(hx);
    float ry = y - __half2float(hy);
    __half2 h2 = __halves2half2(hx, hy);
    __half2 l2 = __halves2half2(__float2half_rn(rx), __float2half_rn(ry));
    hi = *reinterpret_cast<uint32_t*>(&h2);
    lo = *reinterpret_cast<uint32_t*>(&l2);
}
DINLINE uint32_t pack2h(float x, float y) {
    __half2 h2 = __halves2half2(__float2half_rn(x), __float2half_rn(y));
    return *reinterpret_cast<uint32_t*>(&h2);
}

// ===========================================================================
// Prep kernels
// ===========================================================================
__global__ __launch_bounds__(256) void split_x_kernel(const float* __restrict__ x) {
    int i = blockIdx.x * 256 + threadIdx.x;   // one float4
    float4 v = ((const float4*)x)[i];
    uint32_t h0, l0, h1, l1;
    split2h(v.x, v.y, h0, l0);
    split2h(v.z, v.w, h1, l1);
    ((uint2*)g_x_hi)[i] = make_uint2(h0, h1);
    ((uint2*)g_x_lo)[i] = make_uint2(l0, l1);
}

// src [K][N] fp32 -> fp16 single plane, [N][K]
template <int WSEL>
__global__ __launch_bounds__(256) void tsplit_kernel(
    const float* __restrict__ src, int K, int N)
{
    __half* dh = (WSEL == 0) ? g_wq_hi : g_wp_hi;
    __shared__ float T[32][33];
    int k0 = blockIdx.y * 32, n0 = blockIdx.x * 32;
    int tx = threadIdx.x & 31, ty = threadIdx.x >> 5;
#pragma unroll
    for (int i = 0; i < 4; i++)
        T[ty + 8 * i][tx] = src[(size_t)(k0 + ty + 8 * i) * N + n0 + tx];
    __syncthreads();
#pragma unroll
    for (int i = 0; i < 4; i++) {
        float v = T[tx][ty + 8 * i];
        dh[(size_t)(n0 + ty + 8 * i) * K + k0 + tx] = __float2half_rn(v);
    }
}

// ===========================================================================
// fp16 2-term mma.sync GEMM. Block 64x256, 4 warps, warp tile 64x64,
// BK=32, 2-stage cp.async, B-fragment prefetch. A = pair, B = single.
// ===========================================================================
#define PAe 40                       // smem pitch in fp16 elems (80B): conflict-free
#define A_STG (64*PAe)               // 2560 elems per A plane per stage
#define B_STG (256*PAe)              // 10240 elems (single plane)
#define STG_ELEMS (2*A_STG + B_STG)  // 15360 elems
#define GEMM_SMEM_B (2 * STG_ELEMS * 2)   // 61440 bytes

template <bool QKV_EPI>
__global__ __launch_bounds__(128, 2) void mma_gemm_kernel(
    const float* __restrict__ bias, float* __restrict__ out)
{
    const __half* Ah = QKV_EPI ? g_x_hi : g_o_hi;
    const __half* Al = QKV_EPI ? g_x_lo : g_o_lo;
    const __half* Bh = QKV_EPI ? g_wq_hi : g_wp_hi;

    extern __shared__ __half sm[];
    const int tid = threadIdx.x, lane = tid & 31, warp = tid >> 5;
    const int rowBase = blockIdx.y * 64, colBase = blockIdx.x * 256;

    float acc[4][8][4];
#pragma unroll
    for (int i = 0; i < 4; i++)
#pragma unroll
        for (int j = 0; j < 8; j++)
#pragma unroll
            for (int e = 0; e < 4; e++) acc[i][j][e] = 0.f;

    auto issue = [&](int st) {
        if (st < NKT) {
            const int k0 = st * 32;
            __half* base = sm + (st & 1) * STG_ELEMS;
            // A: 64 rows x 32 cols = 256 chunks/plane, 2 iters, both planes
#pragma unroll
            for (int i = 0; i < 2; i++) {
                int id = tid + i * 128;
                int r = id >> 2, c8 = (id & 3) * 8;
                uint32_t d = smem_u32(base + r * PAe + c8);
                size_t s = (size_t)(rowBase + r) * DIM + k0 + c8;
                cp16(d, Ah + s);
                cp16(d + A_STG * 2, Al + s);
            }
            // B: 256 rows x 32 cols = 1024 chunks, hi only -> 8 iters
#pragma unroll
            for (int i = 0; i < 8; i++) {
                int id = tid + i * 128;
                int r = id >> 2, c8 = (id & 3) * 8;
                uint32_t d = smem_u32(base + 2 * A_STG + r * PAe + c8);
                cp16(d, Bh + (size_t)(colBase + r) * DIM + k0 + c8);
            }
        }
        CP_COMMIT();
    };

    issue(0);
    issue(1);

    const int a_ro = (lane & 7) + 8 * ((lane >> 3) & 1);
    const int a_co = 8 * (lane >> 4);
    const int b_ro = (lane & 7) + 8 * (lane >> 4);
    const int b_co = 8 * ((lane >> 3) & 1);

    for (int t = 0; t < NKT; t++) {
        CP_WAIT1();
        __syncthreads();
        const __half* stg = sm + (t & 1) * STG_ELEMS;
        const __half* sAh = stg;
        const __half* sAl = stg + A_STG;
        const __half* sBh = stg + 2 * A_STG;

        // ---- all A fragments for both k16-steps ----
        uint32_t afh[2][4][4], afl[2][4][4];
#pragma unroll
        for (int ks = 0; ks < 2; ks++)
#pragma unroll
            for (int ma = 0; ma < 4; ma++) {
                int off = (ma * 16 + a_ro) * PAe + ks * 16 + a_co;
                ldsm4(afh[ks][ma], smem_u32(sAh + off));
                ldsm4(afl[ks][ma], smem_u32(sAl + off));
            }

        // ---- B fragment double-buffered prefetch over 8 steps ----
        uint32_t bfh[2][4];
        {
            int off0 = (warp * 64 + b_ro) * PAe + b_co;
            ldsm4(bfh[0], smem_u32(sBh + off0));
        }
#pragma unroll
        for (int step = 0; step < 8; step++) {
            const int ks = step >> 2, nb = step & 3;
            const int cur = step & 1, nxt = cur ^ 1;
            if (step < 7) {
                const int s2 = step + 1;
                const int ks2 = s2 >> 2, nb2 = s2 & 3;
                int off = (warp * 64 + nb2 * 16 + b_ro) * PAe + ks2 * 16 + b_co;
                ldsm4(bfh[nxt], smem_u32(sBh + off));
            }
#pragma unroll
            for (int ma = 0; ma < 4; ma++) {
                mma16816h(acc[ma][2*nb],   afh[ks][ma], &bfh[cur][0]);
                mma16816h(acc[ma][2*nb+1], afh[ks][ma], &bfh[cur][2]);
                mma16816h(acc[ma][2*nb],   afl[ks][ma], &bfh[cur][0]);
                mma16816h(acc[ma][2*nb+1], afl[ks][ma], &bfh[cur][2]);
            }
        }
        __syncthreads();
        issue(t + 2);
    }

    // ---------------- epilogue ----------------
    const int g = lane >> 2, tq = lane & 3;
#pragma unroll
    for (int ma = 0; ma < 4; ma++) {
#pragma unroll
        for (int half = 0; half < 2; half++) {
            int row = rowBase + ma * 16 + g + half * 8;
            if (QKV_EPI) {
                int b = row >> 10, srow = row & 1023;
#pragma unroll
                for (int nn = 0; nn < 8; nn++) {
                    int col = colBase + warp * 64 + nn * 8 + 2 * tq;
                    float v0 = acc[ma][nn][half * 2 + 0] + bias[col];
                    float v1 = acc[ma][nn][half * 2 + 1] + bias[col + 1];
                    int which = col / DIM;
                    int rem = col - which * DIM;
                    int h = rem >> 6, d = rem & 63;
                    size_t idx = (((size_t)(b * HEADS + h)) * SEQ + srow) * HDIM + d;
                    if (which == 0) {          // Q: fp16 pair
                        uint32_t hi, lo;
                        split2h(v0, v1, hi, lo);
                        *(uint32_t*)(g_q_hi + idx) = hi;
                        *(uint32_t*)(g_q_lo + idx) = lo;
                    } else if (which == 1) {   // K: fp16 single
                        *(uint32_t*)(g_k_hi + idx) = pack2h(v0, v1);
                    } else {                   // V: fp16 single
                        *(uint32_t*)(g_v_hi + idx) = pack2h(v0, v1);
                    }
                }
            } else {
#pragma unroll
                for (int nn = 0; nn < 8; nn++) {
                    int col = colBase + warp * 64 + nn * 8 + 2 * tq;
                    float2 o;
                    o.x = acc[ma][nn][half * 2 + 0] + bias[col];
                    o.y = acc[ma][nn][half * 2 + 1] + bias[col + 1];
                    *(float2*)(out + (size_t)row * DIM + col) = o;
                }
            }
        }
    }
}

// ===========================================================================
// Flash attention (R14 — best measured): fp16 2-term, Br=64, 4 warps,
// 2 CTAs/SM, cp.async 2-stage KV, fragment prefetch. O -> fp16 pair.
// ===========================================================================
#define QPITCH 72
#define Q_PL (64*QPITCH)                  // 4608 elems per plane
#define KV_STG (2*Q_PL)                   // K + V single planes per stage
#define AT_SMEM_BYTES ((2*Q_PL + 2*KV_STG) * 2)   // 55296 bytes

__global__ __launch_bounds__(128, 2) void attn_kernel()
{
    extern __shared__ __half smb[];
    const int tid = threadIdx.x, lane = tid & 31, warp = tid >> 5;
    const int bh = blockIdx.y, qt = blockIdx.x;
    const int g = lane >> 2, t = lane & 3;
    const float scale = 0.125f;

    const size_t base = (size_t)bh * SEQ * HDIM;
    const __half* qh = g_q_hi + base; const __half* ql = g_q_lo + base;
    const __half* kh = g_k_hi + base;
    const __half* vh = g_v_hi + base;

    __half* Qs_hi = smb;
    __half* Qs_lo = smb + Q_PL;

#pragma unroll
    for (int i = 0; i < 4; i++) {
        int id = tid + i * 128;
        int r = id >> 3, c8 = (id & 7) * 8;
        size_t s = (size_t)(qt * 64 + r) * HDIM + c8;
        cp16(smem_u32(Qs_hi + r * QPITCH + c8), qh + s);
        cp16(smem_u32(Qs_lo + r * QPITCH + c8), ql + s);
    }

    auto issue_kv = [&](int kt) {
        if (kt < SEQ / 64) {
            __half* sb = smb + 2 * Q_PL + (kt & 1) * KV_STG;
#pragma unroll
            for (int i = 0; i < 4; i++) {
                int id = tid + i * 128;
                int r = id >> 3, c8 = (id & 7) * 8;
                int doff = r * QPITCH + c8;
                size_t s = (size_t)(kt * 64 + r) * HDIM + c8;
                cp16(smem_u32(sb + doff),        kh + s);
                cp16(smem_u32(sb + Q_PL + doff), vh + s);
            }
        }
        CP_COMMIT();
    };

    issue_kv(0);
    issue_kv(1);

    CP_WAIT1();
    __syncthreads();

    const int a_row = warp * 16 + (lane & 7) + 8 * ((lane >> 3) & 1);
    const int a_col = 8 * (lane >> 4);
    uint32_t qfh[4][4], qfl[4][4];
#pragma unroll
    for (int ka = 0; ka < 4; ka++) {
        int off = a_row * QPITCH + ka * 16 + a_col;
        ldsm4(qfh[ka], smem_u32(&Qs_hi[off]));
        ldsm4(qfl[ka], smem_u32(&Qs_lo[off]));
    }

    const int k_row = (lane & 7) + 8 * (lane >> 4);
    const int k_col = 8 * ((lane >> 3) & 1);
    const int v_row = (lane & 7) + 8 * ((lane >> 3) & 1);
    const int v_col = 8 * (lane >> 4);

    float m0 = -1e30f, m1 = -1e30f, l0 = 0.f, l1 = 0.f;
    float o[8][4];
#pragma unroll
    for (int j = 0; j < 8; j++)
#pragma unroll
        for (int e = 0; e < 4; e++) o[j][e] = 0.f;

    for (int kt = 0; kt < SEQ / 64; kt++) {
        const __half* sb = smb + 2 * Q_PL + (kt & 1) * KV_STG;
        const __half* Ksh = sb;
        const __half* Vsh = sb + Q_PL;

        // ---- S = (Qh+Ql) Kh^T : K-fragment double buffered ----
        float s[8][4];
#pragma unroll
        for (int j = 0; j < 8; j++)
#pragma unroll
            for (int e = 0; e < 4; e++) s[j][e] = 0.f;

        uint32_t kfh[2][4];
        {
            int off0 = k_row * QPITCH + k_col;
            ldsm4(kfh[0], smem_u32(Ksh + off0));
        }
#pragma unroll
        for (int step = 0; step < 16; step++) {
            const int nb = step >> 2, ka = step & 3;
            const int cur = step & 1, nxt = cur ^ 1;
            if (step < 15) {
                const int s2 = step + 1;
                const int nb2 = s2 >> 2, ka2 = s2 & 3;
                int off = (nb2 * 16 + k_row) * QPITCH + ka2 * 16 + k_col;
                ldsm4(kfh[nxt], smem_u32(Ksh + off));
            }
            mma16816h(s[2*nb],   qfh[ka], &kfh[cur][0]);
            mma16816h(s[2*nb+1], qfh[ka], &kfh[cur][2]);
            mma16816h(s[2*nb],   qfl[ka], &kfh[cur][0]);
            mma16816h(s[2*nb+1], qfl[ka], &kfh[cur][2]);
        }

        // ---- online softmax ----
        float mx0 = -1e30f, mx1 = -1e30f;
#pragma unroll
        for (int j = 0; j < 8; j++) {
            s[j][0] *= scale; s[j][1] *= scale; s[j][2] *= scale; s[j][3] *= scale;
            mx0 = fmaxf(mx0, fmaxf(s[j][0], s[j][1]));
            mx1 = fmaxf(mx1, fmaxf(s[j][2], s[j][3]));
        }
        mx0 = fmaxf(mx0, __shfl_xor_sync(0xffffffffu, mx0, 1));
        mx0 = fmaxf(mx0, __shfl_xor_sync(0xffffffffu, mx0, 2));
        mx1 = fmaxf(mx1, __shfl_xor_sync(0xffffffffu, mx1, 1));
        mx1 = fmaxf(mx1, __shfl_xor_sync(0xffffffffu, mx1, 2));
        float mn0 = fmaxf(m0, mx0), mn1 = fmaxf(m1, mx1);
        float c0 = __expf(m0 - mn0), c1 = __expf(m1 - mn1);
        float p[8][4];
        float ls0 = 0.f, ls1 = 0.f;
#pragma unroll
        for (int j = 0; j < 8; j++) {
            p[j][0] = __expf(s[j][0] - mn0); p[j][1] = __expf(s[j][1] - mn0);
            p[j][2] = __expf(s[j][2] - mn1); p[j][3] = __expf(s[j][3] - mn1);
            ls0 += p[j][0] + p[j][1];
            ls1 += p[j][2] + p[j][3];
        }
        ls0 += __shfl_xor_sync(0xffffffffu, ls0, 1);
        ls0 += __shfl_xor_sync(0xffffffffu, ls0, 2);
        ls1 += __shfl_xor_sync(0xffffffffu, ls1, 1);
        ls1 += __shfl_xor_sync(0xffffffffu, ls1, 2);
        l0 = l0 * c0 + ls0; m0 = mn0;
        l1 = l1 * c1 + ls1; m1 = mn1;
#pragma unroll
        for (int j = 0; j < 8; j++) {
            o[j][0] *= c0; o[j][1] *= c0; o[j][2] *= c1; o[j][3] *= c1;
        }

        // ---- P fragments (fp16 pair) ----
        uint32_t pfh[4][4], pfl[4][4];
#pragma unroll
        for (int ka = 0; ka < 4; ka++) {
            split2h(p[2*ka][0],   p[2*ka][1],   pfh[ka][0], pfl[ka][0]);
            split2h(p[2*ka][2],   p[2*ka][3],   pfh[ka][1], pfl[ka][1]);
            split2h(p[2*ka+1][0], p[2*ka+1][1], pfh[ka][2], pfl[ka][2]);
            split2h(p[2*ka+1][2], p[2*ka+1][3], pfh[ka][3], pfl[ka][3]);
        }

        // ---- O += (Ph+Pl) Vh : V-fragment double buffered ----
        uint32_t vfh[2][4];
        {
            int off0 = v_row * QPITCH + v_col;
            ldsm4t(vfh[0], smem_u32(Vsh + off0));
        }
#pragma unroll
        for (int step = 0; step < 16; step++) {
            const int nb = step >> 2, ka = step & 3;
            const int cur = step & 1, nxt = cur ^ 1;
            if (step < 15) {
                const int s2 = step + 1;
                const int nb2 = s2 >> 2, ka2 = s2 & 3;
                int off = (ka2 * 16 + v_row) * QPITCH + nb2 * 16 + v_col;
                ldsm4t(vfh[nxt], smem_u32(Vsh + off));
            }
            mma16816h(o[2*nb],   pfh[ka], &vfh[cur][0]);
            mma16816h(o[2*nb+1], pfh[ka], &vfh[cur][2]);
            mma16816h(o[2*nb],   pfl[ka], &vfh[cur][0]);
            mma16816h(o[2*nb+1], pfl[ka], &vfh[cur][2]);
        }

        __syncthreads();
        issue_kv(kt + 2);
        CP_WAIT1();
        __syncthreads();
    }

    // ---- normalize + write O as fp16 pair into [B,S,D] planes ----
    float i0 = 1.f / l0, i1 = 1.f / l1;
    int b = bh / HEADS, h = bh - (bh / HEADS) * HEADS;
    int srow0 = qt * 64 + warp * 16 + g;
    int srow1 = srow0 + 8;
#pragma unroll
    for (int j = 0; j < 8; j++) {
        int col = h * HDIM + j * 8 + 2 * t;
        size_t i0x = ((size_t)(b * SEQ) + srow0) * DIM + col;
        size_t i1x = ((size_t)(b * SEQ) + srow1) * DIM + col;
        uint32_t hi, lo;
        split2h(o[j][0] * i0, o[j][1] * i0, hi, lo);
        *(uint32_t*)(g_o_hi + i0x) = hi;
        *(uint32_t*)(g_o_lo + i0x) = lo;
        split2h(o[j][2] * i1, o[j][3] * i1, hi, lo);
        *(uint32_t*)(g_o_hi + i1x) = hi;
        *(uint32_t*)(g_o_lo + i1x) = lo;
    }
}

// ===========================================================================
extern "C" void kernel_launch(void* const* d_in, const int* in_sizes, int n_in,
                              void* d_out, int out_size) {
    const float* x      = (const float*)d_in[0];
    const float* w_qkv  = (const float*)d_in[1];
    const float* b_qkv  = (const float*)d_in[2];
    const float* w_proj = (const float*)d_in[3];
    const float* b_proj = (const float*)d_in[4];
    float* out = (float*)d_out;

    cudaFuncSetAttribute(attn_kernel, cudaFuncAttributeMaxDynamicSharedMemorySize,
                         AT_SMEM_BYTES);
    cudaFuncSetAttribute(mma_gemm_kernel<true>, cudaFuncAttributeMaxDynamicSharedMemorySize,
                         GEMM_SMEM_B);
    cudaFuncSetAttribute(mma_gemm_kernel<false>, cudaFuncAttributeMaxDynamicSharedMemorySize,
                         GEMM_SMEM_B);

    // prep
    split_x_kernel<<<M_ROWS * DIM / 1024, 256>>>(x);
    tsplit_kernel<0><<<dim3(N_QKV / 32, DIM / 32), 256>>>(w_qkv, DIM, N_QKV);
    tsplit_kernel<1><<<dim3(DIM / 32, DIM / 32), 256>>>(w_proj, DIM, DIM);

    // QKV GEMM: M=8192, N=2304
    mma_gemm_kernel<true><<<dim3(N_QKV / 256, M_ROWS / 64), 128, GEMM_SMEM_B>>>(
        b_qkv, nullptr);

    // attention
    attn_kernel<<<dim3(SEQ / 64, BATCH * HEADS), 128, AT_SMEM_BYTES>>>();

    // proj GEMM: M=8192, N=768
    mma_gemm_kernel<false><<<dim3(DIM / 256, M_ROWS / 64), 128, GEMM_SMEM_B>>>(
        b_proj, out);
}